// round 7
// baseline (speedup 1.0000x reference)
#include <cuda_runtime.h>
#include <cuda_bf16.h>

// Problem constants (fixed by the reference)
#define NODES 100000
#define EDGES 1600000
#define IN_C  128
#define HID_C 128
#define OUT_C 64

// -------- scratch (no allocation allowed -> __device__ globals) --------
__device__ float g_deg[NODES];
__device__ float g_deginv[NODES];
__device__ float g_h1[NODES * HID_C];    // scaled projection, layer 1
__device__ float g_out1[NODES * HID_C];  // aggregated layer-1 output (init to b1)
__device__ float g_h2[NODES * OUT_C];    // scaled projection, layer 2

// vectorized no-return global reduction (REDG pipe, 16B/op)
__device__ __forceinline__ void red_add_v4(float4* p, float4 v) {
    asm volatile("red.global.add.v4.f32 [%0], {%1, %2, %3, %4};"
                 :: "l"(p), "f"(v.x), "f"(v.y), "f"(v.z), "f"(v.w)
                 : "memory");
}

// -------- init: out1 <- b1 broadcast, out <- b2 broadcast, deg <- 0 --------
__global__ void init_kernel(const float* __restrict__ b1,
                            const float* __restrict__ b2,
                            float* __restrict__ outp) {
    int i = blockIdx.x * blockDim.x + threadIdx.x;
    if (i < NODES * HID_C) g_out1[i] = b1[i & (HID_C - 1)];
    if (i < NODES * OUT_C) outp[i]   = b2[i & (OUT_C - 1)];
    if (i < NODES)         g_deg[i]  = 0.0f;
}

// -------- out-degree via scalar RED --------
__global__ void degree_kernel(const int* __restrict__ src) {
    int i = blockIdx.x * blockDim.x + threadIdx.x;
    if (i < EDGES) atomicAdd(&g_deg[src[i]], 1.0f);
}

__global__ void deginv_kernel() {
    int i = blockIdx.x * blockDim.x + threadIdx.x;
    if (i < NODES) g_deginv[i] = 1.0f / fmaxf(g_deg[i], 1.0f);
}

// -------- tiled SGEMM: C[M,NOUT] = op(A[M,128]) @ B[128,NOUT], then *deg_inv ----
// BM=128, BK=8, BN=NOUT (64 or 128). 8x8 microtile per thread.
// Threads = (BN/8) * 16.  FLOP:LDS-byte = 2:1  -> fma-pipe bound (not smem bound).
// SECOND: A = relu(g_out1) (bias folded into init), C = g_h2. else A = x, C = g_h1.
template <int BN, bool SECOND>
__global__ __launch_bounds__(BN * 2) void gemm_kernel(const float* __restrict__ Ain,
                                                      const float* __restrict__ B,
                                                      int M) {
    constexpr int BM = 128;
    constexpr int BK = 8;
    constexpr int NTX = BN / 8;          // thread cols (8 or 16)
    constexpr int THREADS = NTX * 16;    // 128 or 256

    const float* A = SECOND ? g_out1 : Ain;
    float*       C = SECOND ? g_h2   : g_h1;

    __shared__ float As[BK][BM];   // k-major (transposed on store)
    __shared__ float Bs[BK][BN];

    const int tid = threadIdx.x;
    const int tx = tid % NTX;            // col group (8 cols each)
    const int ty = tid / NTX;            // row group (8 rows each), 0..15
    const int rowBase = blockIdx.y * BM;

    float acc[8][8];
#pragma unroll
    for (int i = 0; i < 8; i++)
#pragma unroll
        for (int j = 0; j < 8; j++) acc[i][j] = 0.0f;

    for (int k0 = 0; k0 < 128; k0 += BK) {
        // ---- load A tile: BM x BK floats, transposed into As[k][row] ----
#pragma unroll
        for (int i = tid; i < BM * BK / 4; i += THREADS) {
            int lrow = i >> 1;           // 0..127  (BK/4 == 2 quads per row)
            int kq   = i & 1;            // which k-quad
            int grow = rowBase + lrow;
            float4 a = make_float4(0.f, 0.f, 0.f, 0.f);
            if (grow < M)
                a = *reinterpret_cast<const float4*>(A + (size_t)grow * 128 + k0 + kq * 4);
            if (SECOND) {
                a.x = fmaxf(a.x, 0.f); a.y = fmaxf(a.y, 0.f);
                a.z = fmaxf(a.z, 0.f); a.w = fmaxf(a.w, 0.f);
            }
            As[kq * 4 + 0][lrow] = a.x;
            As[kq * 4 + 1][lrow] = a.y;
            As[kq * 4 + 2][lrow] = a.z;
            As[kq * 4 + 3][lrow] = a.w;
        }
        // ---- load B tile: BK x BN floats ----
#pragma unroll
        for (int i = tid; i < BK * BN / 4; i += THREADS) {
            int krow = i / (BN / 4);
            int cq   = i % (BN / 4);
            float4 b = *reinterpret_cast<const float4*>(B + (size_t)(k0 + krow) * BN + cq * 4);
            *reinterpret_cast<float4*>(&Bs[krow][cq * 4]) = b;
        }
        __syncthreads();

#pragma unroll
        for (int k = 0; k < BK; k++) {
            float4 a0 = *reinterpret_cast<const float4*>(&As[k][ty * 8]);
            float4 a1 = *reinterpret_cast<const float4*>(&As[k][ty * 8 + 4]);
            float4 b0 = *reinterpret_cast<const float4*>(&Bs[k][tx * 8]);
            float4 b1 = *reinterpret_cast<const float4*>(&Bs[k][tx * 8 + 4]);
            float a[8] = {a0.x, a0.y, a0.z, a0.w, a1.x, a1.y, a1.z, a1.w};
            float b[8] = {b0.x, b0.y, b0.z, b0.w, b1.x, b1.y, b1.z, b1.w};
#pragma unroll
            for (int i = 0; i < 8; i++)
#pragma unroll
                for (int j = 0; j < 8; j++) acc[i][j] += a[i] * b[j];
        }
        __syncthreads();
    }

    // ---- epilogue: scale by deg_inv[row], store ----
#pragma unroll
    for (int i = 0; i < 8; i++) {
        int row = rowBase + ty * 8 + i;
        if (row < M) {
            float s = g_deginv[row];
            float4 o0 = make_float4(acc[i][0] * s, acc[i][1] * s, acc[i][2] * s, acc[i][3] * s);
            float4 o1 = make_float4(acc[i][4] * s, acc[i][5] * s, acc[i][6] * s, acc[i][7] * s);
            float* crow = C + (size_t)row * BN + tx * 8;
            *reinterpret_cast<float4*>(crow)     = o0;
            *reinterpret_cast<float4*>(crow + 4) = o1;
        }
    }
}

// -------- layer-1 scatter: warp per edge, 32 x float4 = 128 floats --------
__global__ void scatter128_kernel(const int* __restrict__ src,
                                  const int* __restrict__ dst) {
    int gtid = blockIdx.x * blockDim.x + threadIdx.x;
    int e = gtid >> 5;
    int lane = gtid & 31;
    if (e >= EDGES) return;
    int s = src[e];
    int d = dst[e];
    float4 v = reinterpret_cast<const float4*>(g_h1)[s * 32 + lane];
    red_add_v4(reinterpret_cast<float4*>(g_out1) + d * 32 + lane, v);
}

// -------- layer-2 scatter: half-warp per edge, 16 x float4 = 64 floats --------
__global__ void scatter64_kernel(const int* __restrict__ src,
                                 const int* __restrict__ dst,
                                 float* __restrict__ outp) {
    int gtid = blockIdx.x * blockDim.x + threadIdx.x;
    int e = gtid >> 4;
    int lane = gtid & 15;
    if (e >= EDGES) return;
    int s = src[e];
    int d = dst[e];
    float4 v = reinterpret_cast<const float4*>(g_h2)[s * 16 + lane];
    red_add_v4(reinterpret_cast<float4*>(outp) + d * 16 + lane, v);
}

extern "C" void kernel_launch(void* const* d_in, const int* in_sizes, int n_in,
                              void* d_out, int out_size) {
    const float* x  = (const float*)d_in[0];
    const int*   ei = (const int*)d_in[1];   // [2, E]: src then dst
    const float* W1 = (const float*)d_in[2];
    const float* b1 = (const float*)d_in[3];
    const float* W2 = (const float*)d_in[4];
    const float* b2 = (const float*)d_in[5];
    float* outp = (float*)d_out;

    const int* src = ei;
    const int* dst = ei + EDGES;

    // 1) init accumulators (bias broadcast) + zero degrees
    init_kernel<<<(NODES * HID_C + 255) / 256, 256>>>(b1, b2, outp);
    // 2) out-degrees
    degree_kernel<<<(EDGES + 255) / 256, 256>>>(src);
    // 3) reciprocal
    deginv_kernel<<<(NODES + 255) / 256, 256>>>();
    // 4) h1 = (x @ W1) * deg_inv   (BM=128, BN=128, 256 thr, 8x8 microtile)
    {
        dim3 grid(1, (NODES + 127) / 128);
        gemm_kernel<HID_C, false><<<grid, 256>>>(x, W1, NODES);
    }
    // 5) out1 += scatter h1[src] -> dst  (v4 global reductions)
    {
        long long threads = (long long)EDGES * 32;
        scatter128_kernel<<<(unsigned)((threads + 255) / 256), 256>>>(src, dst);
    }
    // 6) h2 = (relu(out1) @ W2) * deg_inv   (BM=128, BN=64, 128 thr, 8x8 microtile)
    {
        dim3 grid(1, (NODES + 127) / 128);
        gemm_kernel<OUT_C, true><<<grid, 128>>>(nullptr, W2, NODES);
    }
    // 7) out += scatter h2[src] -> dst
    {
        long long threads = (long long)EDGES * 16;
        scatter64_kernel<<<(unsigned)((threads + 255) / 256), 256>>>(src, dst, outp);
    }
}

// round 9
// speedup vs baseline: 1.1250x; 1.1250x over previous
#include <cuda_runtime.h>
#include <cuda_bf16.h>

// Problem constants (fixed by the reference)
#define NODES 100000
#define EDGES 1600000
#define IN_C  128
#define HID_C 128
#define OUT_C 64

#define SCAN_B 1024
#define SCAN_NB ((NODES + SCAN_B - 1) / SCAN_B)   // 98

// -------- scratch (no allocation allowed -> __device__ globals) --------
__device__ int   g_odeg[NODES];          // out-degree (src histogram)
__device__ float g_deginv[NODES];
__device__ int   g_cnt[NODES];           // in-degree (dst histogram)
__device__ int   g_off[NODES + 1];       // CSR offsets (by dst)
__device__ int   g_cur[NODES];           // fill cursors
__device__ int   g_csr[EDGES];           // src ids grouped by dst
__device__ int   g_bsum[SCAN_NB + 1];    // scan block sums
__device__ float g_h1[NODES * HID_C];    // scaled projection, layer 1
__device__ float g_out1[NODES * HID_C];  // relu input (aggregated + b1)
__device__ float g_h2[NODES * OUT_C];    // scaled projection, layer 2

// -------- init: zero both histograms --------
__global__ void init_kernel() {
    int i = blockIdx.x * blockDim.x + threadIdx.x;
    if (i < NODES) { g_odeg[i] = 0; g_cnt[i] = 0; }
}

// -------- histograms: out-degree of src, in-degree of dst --------
__global__ void hist_kernel(const int* __restrict__ src,
                            const int* __restrict__ dst) {
    int i = blockIdx.x * blockDim.x + threadIdx.x;
    if (i < EDGES) {
        atomicAdd(&g_odeg[src[i]], 1);
        atomicAdd(&g_cnt[dst[i]], 1);
    }
}

__global__ void deginv_kernel() {
    int i = blockIdx.x * blockDim.x + threadIdx.x;
    if (i < NODES) g_deginv[i] = 1.0f / fmaxf((float)g_odeg[i], 1.0f);
}

// -------- 3-kernel exclusive scan of g_cnt -> g_off --------
__global__ __launch_bounds__(SCAN_B) void scan1_kernel() {
    int gi = blockIdx.x * SCAN_B + threadIdx.x;
    int v = (gi < NODES) ? g_cnt[gi] : 0;
    int lane = threadIdx.x & 31, w = threadIdx.x >> 5;
    // warp inclusive scan
    int x = v;
#pragma unroll
    for (int o = 1; o < 32; o <<= 1) {
        int y = __shfl_up_sync(0xffffffffu, x, o);
        if (lane >= o) x += y;
    }
    __shared__ int wsum[32];
    if (lane == 31) wsum[w] = x;
    __syncthreads();
    if (w == 0) {
        int s = wsum[lane];
#pragma unroll
        for (int o = 1; o < 32; o <<= 1) {
            int y = __shfl_up_sync(0xffffffffu, s, o);
            if (lane >= o) s += y;
        }
        wsum[lane] = s;
    }
    __syncthreads();
    int incl = x + (w > 0 ? wsum[w - 1] : 0);
    if (gi < NODES) g_off[gi] = incl - v;           // block-local exclusive
    if (threadIdx.x == SCAN_B - 1) g_bsum[blockIdx.x] = incl;
}

__global__ void scan2_kernel() {
    if (threadIdx.x == 0) {
        int run = 0;
        for (int b = 0; b < SCAN_NB; b++) {
            int t = g_bsum[b];
            g_bsum[b] = run;
            run += t;
        }
    }
}

__global__ __launch_bounds__(SCAN_B) void scan3_kernel() {
    int gi = blockIdx.x * SCAN_B + threadIdx.x;
    if (gi < NODES) {
        int o = g_off[gi] + g_bsum[blockIdx.x];
        g_off[gi] = o;
        g_cur[gi] = o;
    }
    if (gi == 0) g_off[NODES] = EDGES;
}

// -------- CSR fill: bucket src ids by dst --------
__global__ void fill_kernel(const int* __restrict__ src,
                            const int* __restrict__ dst) {
    int i = blockIdx.x * blockDim.x + threadIdx.x;
    if (i < EDGES) {
        int p = atomicAdd(&g_cur[dst[i]], 1);
        g_csr[p] = src[i];
    }
}

// -------- tiled SGEMM (round-5 config): BM=BN=64, BK=16, 4x4 microtile ----
// SECOND: A = relu(g_out1), C = g_h2. else A = x param, C = g_h1.
template <int NOUT, bool SECOND>
__global__ __launch_bounds__(256) void gemm_kernel(const float* __restrict__ Ain,
                                                   const float* __restrict__ B,
                                                   int M) {
    const float* A = SECOND ? g_out1 : Ain;
    float*       C = SECOND ? g_h2   : g_h1;

    __shared__ float As[16][64];  // transposed: As[k][row]
    __shared__ float Bs[16][64];

    const int tid = threadIdx.x;
    const int tx = tid & 15;
    const int ty = tid >> 4;
    const int rowBase = blockIdx.y * 64;
    const int colBase = blockIdx.x * 64;

    const int ar = tid >> 2;
    const int ac = tid & 3;
    const int br = tid >> 4;
    const int bc = tid & 15;

    float acc[4][4];
#pragma unroll
    for (int i = 0; i < 4; i++)
#pragma unroll
        for (int j = 0; j < 4; j++) acc[i][j] = 0.0f;

    for (int k0 = 0; k0 < 128; k0 += 16) {
        {
            int grow = rowBase + ar;
            float4 a = make_float4(0.f, 0.f, 0.f, 0.f);
            if (grow < M)
                a = reinterpret_cast<const float4*>(A + (size_t)grow * 128 + k0)[ac];
            if (SECOND) {
                a.x = fmaxf(a.x, 0.f); a.y = fmaxf(a.y, 0.f);
                a.z = fmaxf(a.z, 0.f); a.w = fmaxf(a.w, 0.f);
            }
            As[ac * 4 + 0][ar] = a.x;
            As[ac * 4 + 1][ar] = a.y;
            As[ac * 4 + 2][ar] = a.z;
            As[ac * 4 + 3][ar] = a.w;
        }
        {
            float4 b = reinterpret_cast<const float4*>(B + (size_t)(k0 + br) * NOUT + colBase)[bc];
            *reinterpret_cast<float4*>(&Bs[br][bc * 4]) = b;
        }
        __syncthreads();

#pragma unroll
        for (int k = 0; k < 16; k++) {
            float4 av = *reinterpret_cast<float4*>(&As[k][ty * 4]);
            float4 bv = *reinterpret_cast<float4*>(&Bs[k][tx * 4]);
            float a[4] = {av.x, av.y, av.z, av.w};
            float b[4] = {bv.x, bv.y, bv.z, bv.w};
#pragma unroll
            for (int i = 0; i < 4; i++)
#pragma unroll
                for (int j = 0; j < 4; j++) acc[i][j] += a[i] * b[j];
        }
        __syncthreads();
    }

#pragma unroll
    for (int i = 0; i < 4; i++) {
        int row = rowBase + ty * 4 + i;
        if (row < M) {
            float s = g_deginv[row];
            float4 o = make_float4(acc[i][0] * s, acc[i][1] * s, acc[i][2] * s, acc[i][3] * s);
            *reinterpret_cast<float4*>(C + (size_t)row * NOUT + colBase + tx * 4) = o;
        }
    }
}

// -------- layer-1 aggregate: warp per dst node, 32 x float4 = 128 ch --------
__global__ __launch_bounds__(256) void agg128_kernel(const float* __restrict__ b1) {
    int gw = (blockIdx.x * blockDim.x + threadIdx.x) >> 5;
    int lane = threadIdx.x & 31;
    if (gw >= NODES) return;
    int beg = g_off[gw], end = g_off[gw + 1];
    const float4* __restrict__ H = reinterpret_cast<const float4*>(g_h1);

    float4 a0 = make_float4(0.f, 0.f, 0.f, 0.f);
    float4 a1 = make_float4(0.f, 0.f, 0.f, 0.f);
    int e = beg;
    for (; e + 1 < end; e += 2) {
        int s0 = g_csr[e], s1 = g_csr[e + 1];
        float4 v0 = H[s0 * 32 + lane];
        float4 v1 = H[s1 * 32 + lane];
        a0.x += v0.x; a0.y += v0.y; a0.z += v0.z; a0.w += v0.w;
        a1.x += v1.x; a1.y += v1.y; a1.z += v1.z; a1.w += v1.w;
    }
    if (e < end) {
        int s = g_csr[e];
        float4 v = H[s * 32 + lane];
        a0.x += v.x; a0.y += v.y; a0.z += v.z; a0.w += v.w;
    }
    float4 bv = reinterpret_cast<const float4*>(b1)[lane];
    float4 o = make_float4(a0.x + a1.x + bv.x, a0.y + a1.y + bv.y,
                           a0.z + a1.z + bv.z, a0.w + a1.w + bv.w);
    reinterpret_cast<float4*>(g_out1)[gw * 32 + lane] = o;
}

// -------- layer-2 aggregate: warp per dst node, 32 x float2 = 64 ch --------
__global__ __launch_bounds__(256) void agg64_kernel(const float* __restrict__ b2,
                                                    float* __restrict__ outp) {
    int gw = (blockIdx.x * blockDim.x + threadIdx.x) >> 5;
    int lane = threadIdx.x & 31;
    if (gw >= NODES) return;
    int beg = g_off[gw], end = g_off[gw + 1];
    const float2* __restrict__ H = reinterpret_cast<const float2*>(g_h2);

    float2 a0 = make_float2(0.f, 0.f);
    float2 a1 = make_float2(0.f, 0.f);
    int e = beg;
    for (; e + 1 < end; e += 2) {
        int s0 = g_csr[e], s1 = g_csr[e + 1];
        float2 v0 = H[s0 * 32 + lane];
        float2 v1 = H[s1 * 32 + lane];
        a0.x += v0.x; a0.y += v0.y;
        a1.x += v1.x; a1.y += v1.y;
    }
    if (e < end) {
        int s = g_csr[e];
        float2 v = H[s * 32 + lane];
        a0.x += v.x; a0.y += v.y;
    }
    float2 bv = reinterpret_cast<const float2*>(b2)[lane];
    float2 o = make_float2(a0.x + a1.x + bv.x, a0.y + a1.y + bv.y);
    reinterpret_cast<float2*>(outp)[gw * 32 + lane] = o;
}

extern "C" void kernel_launch(void* const* d_in, const int* in_sizes, int n_in,
                              void* d_out, int out_size) {
    const float* x  = (const float*)d_in[0];
    const int*   ei = (const int*)d_in[1];   // [2, E]: src then dst
    const float* W1 = (const float*)d_in[2];
    const float* b1 = (const float*)d_in[3];
    const float* W2 = (const float*)d_in[4];
    const float* b2 = (const float*)d_in[5];
    float* outp = (float*)d_out;

    const int* src = ei;
    const int* dst = ei + EDGES;

    // ---- CSR build (reused by both layers) + out-degree ----
    init_kernel<<<(NODES + 255) / 256, 256>>>();
    hist_kernel<<<(EDGES + 255) / 256, 256>>>(src, dst);
    deginv_kernel<<<(NODES + 255) / 256, 256>>>();
    scan1_kernel<<<SCAN_NB, SCAN_B>>>();
    scan2_kernel<<<1, 32>>>();
    scan3_kernel<<<SCAN_NB, SCAN_B>>>();
    fill_kernel<<<(EDGES + 255) / 256, 256>>>(src, dst);

    // ---- layer 1: h1 = (x @ W1) * deg_inv ; out1 = b1 + sum_in h1 ----
    {
        dim3 grid(HID_C / 64, (NODES + 63) / 64);
        gemm_kernel<HID_C, false><<<grid, 256>>>(x, W1, NODES);
    }
    {
        long long threads = (long long)NODES * 32;
        agg128_kernel<<<(unsigned)((threads + 255) / 256), 256>>>(b1);
    }

    // ---- layer 2: h2 = (relu(out1) @ W2) * deg_inv ; out = b2 + sum_in h2 ----
    {
        dim3 grid(OUT_C / 64, (NODES + 63) / 64);
        gemm_kernel<OUT_C, true><<<grid, 256>>>(nullptr, W2, NODES);
    }
    {
        long long threads = (long long)NODES * 32;
        agg64_kernel<<<(unsigned)((threads + 255) / 256), 256>>>(b2, outp);
    }
}

// round 10
// speedup vs baseline: 1.6036x; 1.4255x over previous
#include <cuda_runtime.h>
#include <cuda_bf16.h>

// Problem constants (fixed by the reference)
#define NODES 100000
#define EDGES 1600000
#define IN_C  128
#define HID_C 128
#define OUT_C 64

#define SCAN_B 1024
#define SCAN_NB ((NODES + SCAN_B - 1) / SCAN_B)   // 98

// -------- scratch (no allocation allowed -> __device__ globals) --------
__device__ int   g_odeg[NODES];          // out-degree (src histogram)
__device__ float g_deginv[NODES];
__device__ int   g_cnt[NODES];           // in-degree (dst histogram)
__device__ int   g_off[NODES + 1];       // CSR offsets (by dst)
__device__ int   g_cur[NODES];           // fill cursors
__device__ int   g_csr[EDGES];           // src ids grouped by dst
__device__ int   g_bsum[SCAN_NB + 1];    // scan block sums
__device__ float g_h1[NODES * HID_C];    // scaled projection, layer 1
__device__ float g_out1[NODES * HID_C];  // relu input (aggregated + b1)
__device__ float g_h2[NODES * OUT_C];    // scaled projection, layer 2

// -------- init: zero both histograms --------
__global__ void init_kernel() {
    int i = blockIdx.x * blockDim.x + threadIdx.x;
    if (i < NODES) { g_odeg[i] = 0; g_cnt[i] = 0; }
}

// -------- histograms: out-degree of src, in-degree of dst --------
__global__ void hist_kernel(const int* __restrict__ src,
                            const int* __restrict__ dst) {
    int i = blockIdx.x * blockDim.x + threadIdx.x;
    if (i < EDGES) {
        atomicAdd(&g_odeg[src[i]], 1);
        atomicAdd(&g_cnt[dst[i]], 1);
    }
}

__global__ void deginv_kernel() {
    int i = blockIdx.x * blockDim.x + threadIdx.x;
    if (i < NODES) g_deginv[i] = 1.0f / fmaxf((float)g_odeg[i], 1.0f);
}

// -------- 3-kernel exclusive scan of g_cnt -> g_off --------
__global__ __launch_bounds__(SCAN_B) void scan1_kernel() {
    int gi = blockIdx.x * SCAN_B + threadIdx.x;
    int v = (gi < NODES) ? g_cnt[gi] : 0;
    int lane = threadIdx.x & 31, w = threadIdx.x >> 5;
    int x = v;
#pragma unroll
    for (int o = 1; o < 32; o <<= 1) {
        int y = __shfl_up_sync(0xffffffffu, x, o);
        if (lane >= o) x += y;
    }
    __shared__ int wsum[32];
    if (lane == 31) wsum[w] = x;
    __syncthreads();
    if (w == 0) {
        int s = wsum[lane];
#pragma unroll
        for (int o = 1; o < 32; o <<= 1) {
            int y = __shfl_up_sync(0xffffffffu, s, o);
            if (lane >= o) s += y;
        }
        wsum[lane] = s;
    }
    __syncthreads();
    int incl = x + (w > 0 ? wsum[w - 1] : 0);
    if (gi < NODES) g_off[gi] = incl - v;           // block-local exclusive
    if (threadIdx.x == SCAN_B - 1) g_bsum[blockIdx.x] = incl;
}

__global__ void scan2_kernel() {
    if (threadIdx.x == 0) {
        int run = 0;
        for (int b = 0; b < SCAN_NB; b++) {
            int t = g_bsum[b];
            g_bsum[b] = run;
            run += t;
        }
    }
}

__global__ __launch_bounds__(SCAN_B) void scan3_kernel() {
    int gi = blockIdx.x * SCAN_B + threadIdx.x;
    if (gi < NODES) {
        int o = g_off[gi] + g_bsum[blockIdx.x];
        g_off[gi] = o;
        g_cur[gi] = o;
    }
    if (gi == 0) g_off[NODES] = EDGES;
}

// -------- CSR fill: bucket src ids by dst --------
__global__ void fill_kernel(const int* __restrict__ src,
                            const int* __restrict__ dst) {
    int i = blockIdx.x * blockDim.x + threadIdx.x;
    if (i < EDGES) {
        int p = atomicAdd(&g_cur[dst[i]], 1);
        g_csr[p] = src[i];
    }
}

// -------- tiled SGEMM (round-5 config): BM=BN=64, BK=16, 4x4 microtile ----
// SECOND: A = relu(g_out1), C = g_h2. else A = x param, C = g_h1.
template <int NOUT, bool SECOND>
__global__ __launch_bounds__(256) void gemm_kernel(const float* __restrict__ Ain,
                                                   const float* __restrict__ B,
                                                   int M) {
    const float* A = SECOND ? g_out1 : Ain;
    float*       C = SECOND ? g_h2   : g_h1;

    __shared__ float As[16][64];  // transposed: As[k][row]
    __shared__ float Bs[16][64];

    const int tid = threadIdx.x;
    const int tx = tid & 15;
    const int ty = tid >> 4;
    const int rowBase = blockIdx.y * 64;
    const int colBase = blockIdx.x * 64;

    const int ar = tid >> 2;
    const int ac = tid & 3;
    const int br = tid >> 4;
    const int bc = tid & 15;

    float acc[4][4];
#pragma unroll
    for (int i = 0; i < 4; i++)
#pragma unroll
        for (int j = 0; j < 4; j++) acc[i][j] = 0.0f;

    for (int k0 = 0; k0 < 128; k0 += 16) {
        {
            int grow = rowBase + ar;
            float4 a = make_float4(0.f, 0.f, 0.f, 0.f);
            if (grow < M)
                a = reinterpret_cast<const float4*>(A + (size_t)grow * 128 + k0)[ac];
            if (SECOND) {
                a.x = fmaxf(a.x, 0.f); a.y = fmaxf(a.y, 0.f);
                a.z = fmaxf(a.z, 0.f); a.w = fmaxf(a.w, 0.f);
            }
            As[ac * 4 + 0][ar] = a.x;
            As[ac * 4 + 1][ar] = a.y;
            As[ac * 4 + 2][ar] = a.z;
            As[ac * 4 + 3][ar] = a.w;
        }
        {
            float4 b = reinterpret_cast<const float4*>(B + (size_t)(k0 + br) * NOUT + colBase)[bc];
            *reinterpret_cast<float4*>(&Bs[br][bc * 4]) = b;
        }
        __syncthreads();

#pragma unroll
        for (int k = 0; k < 16; k++) {
            float4 av = *reinterpret_cast<float4*>(&As[k][ty * 4]);
            float4 bv = *reinterpret_cast<float4*>(&Bs[k][tx * 4]);
            float a[4] = {av.x, av.y, av.z, av.w};
            float b[4] = {bv.x, bv.y, bv.z, bv.w};
#pragma unroll
            for (int i = 0; i < 4; i++)
#pragma unroll
                for (int j = 0; j < 4; j++) acc[i][j] += a[i] * b[j];
        }
        __syncthreads();
    }

#pragma unroll
    for (int i = 0; i < 4; i++) {
        int row = rowBase + ty * 4 + i;
        if (row < M) {
            float s = g_deginv[row];
            float4 o = make_float4(acc[i][0] * s, acc[i][1] * s, acc[i][2] * s, acc[i][3] * s);
            *reinterpret_cast<float4*>(C + (size_t)row * NOUT + colBase + tx * 4) = o;
        }
    }
}

// -------- layer-1 aggregate: warp per dst node, 32 x float4 = 128 ch ------
// 4-wide edge unroll -> 4 independent row loads in flight per lane (MLP=4).
__global__ __launch_bounds__(256) void agg128_kernel(const float* __restrict__ b1) {
    int gw = (blockIdx.x * blockDim.x + threadIdx.x) >> 5;
    int lane = threadIdx.x & 31;
    if (gw >= NODES) return;
    int beg = g_off[gw], end = g_off[gw + 1];
    const float4* __restrict__ H = reinterpret_cast<const float4*>(g_h1);

    float4 a0 = make_float4(0.f, 0.f, 0.f, 0.f);
    float4 a1 = make_float4(0.f, 0.f, 0.f, 0.f);
    float4 a2 = make_float4(0.f, 0.f, 0.f, 0.f);
    float4 a3 = make_float4(0.f, 0.f, 0.f, 0.f);
    int e = beg;
    for (; e + 3 < end; e += 4) {
        int s0 = g_csr[e];
        int s1 = g_csr[e + 1];
        int s2 = g_csr[e + 2];
        int s3 = g_csr[e + 3];
        float4 v0 = H[s0 * 32 + lane];
        float4 v1 = H[s1 * 32 + lane];
        float4 v2 = H[s2 * 32 + lane];
        float4 v3 = H[s3 * 32 + lane];
        a0.x += v0.x; a0.y += v0.y; a0.z += v0.z; a0.w += v0.w;
        a1.x += v1.x; a1.y += v1.y; a1.z += v1.z; a1.w += v1.w;
        a2.x += v2.x; a2.y += v2.y; a2.z += v2.z; a2.w += v2.w;
        a3.x += v3.x; a3.y += v3.y; a3.z += v3.z; a3.w += v3.w;
    }
    for (; e < end; e++) {
        int s = g_csr[e];
        float4 v = H[s * 32 + lane];
        a0.x += v.x; a0.y += v.y; a0.z += v.z; a0.w += v.w;
    }
    float4 bv = reinterpret_cast<const float4*>(b1)[lane];
    float4 o = make_float4(a0.x + a1.x + a2.x + a3.x + bv.x,
                           a0.y + a1.y + a2.y + a3.y + bv.y,
                           a0.z + a1.z + a2.z + a3.z + bv.z,
                           a0.w + a1.w + a2.w + a3.w + bv.w);
    reinterpret_cast<float4*>(g_out1)[gw * 32 + lane] = o;
}

// -------- layer-2 aggregate: HALF-warp per dst node, 16 x float4 = 64 ch --
// Full 16B vector loads (vs float2 before) + 4-wide edge unroll.
__global__ __launch_bounds__(256) void agg64_kernel(const float* __restrict__ b2,
                                                    float* __restrict__ outp) {
    int ghw = (blockIdx.x * blockDim.x + threadIdx.x) >> 4;   // half-warp id
    int lane = threadIdx.x & 15;
    if (ghw >= NODES) return;
    int beg = g_off[ghw], end = g_off[ghw + 1];
    const float4* __restrict__ H = reinterpret_cast<const float4*>(g_h2);

    float4 a0 = make_float4(0.f, 0.f, 0.f, 0.f);
    float4 a1 = make_float4(0.f, 0.f, 0.f, 0.f);
    float4 a2 = make_float4(0.f, 0.f, 0.f, 0.f);
    float4 a3 = make_float4(0.f, 0.f, 0.f, 0.f);
    int e = beg;
    for (; e + 3 < end; e += 4) {
        int s0 = g_csr[e];
        int s1 = g_csr[e + 1];
        int s2 = g_csr[e + 2];
        int s3 = g_csr[e + 3];
        float4 v0 = H[s0 * 16 + lane];
        float4 v1 = H[s1 * 16 + lane];
        float4 v2 = H[s2 * 16 + lane];
        float4 v3 = H[s3 * 16 + lane];
        a0.x += v0.x; a0.y += v0.y; a0.z += v0.z; a0.w += v0.w;
        a1.x += v1.x; a1.y += v1.y; a1.z += v1.z; a1.w += v1.w;
        a2.x += v2.x; a2.y += v2.y; a2.z += v2.z; a2.w += v2.w;
        a3.x += v3.x; a3.y += v3.y; a3.z += v3.z; a3.w += v3.w;
    }
    for (; e < end; e++) {
        int s = g_csr[e];
        float4 v = H[s * 16 + lane];
        a0.x += v.x; a0.y += v.y; a0.z += v.z; a0.w += v.w;
    }
    float4 bv = reinterpret_cast<const float4*>(b2)[lane];
    float4 o = make_float4(a0.x + a1.x + a2.x + a3.x + bv.x,
                           a0.y + a1.y + a2.y + a3.y + bv.y,
                           a0.z + a1.z + a2.z + a3.z + bv.z,
                           a0.w + a1.w + a2.w + a3.w + bv.w);
    reinterpret_cast<float4*>(outp)[ghw * 16 + lane] = o;
}

extern "C" void kernel_launch(void* const* d_in, const int* in_sizes, int n_in,
                              void* d_out, int out_size) {
    const float* x  = (const float*)d_in[0];
    const int*   ei = (const int*)d_in[1];   // [2, E]: src then dst
    const float* W1 = (const float*)d_in[2];
    const float* b1 = (const float*)d_in[3];
    const float* W2 = (const float*)d_in[4];
    const float* b2 = (const float*)d_in[5];
    float* outp = (float*)d_out;

    const int* src = ei;
    const int* dst = ei + EDGES;

    // ---- CSR build (reused by both layers) + out-degree ----
    init_kernel<<<(NODES + 255) / 256, 256>>>();
    hist_kernel<<<(EDGES + 255) / 256, 256>>>(src, dst);
    deginv_kernel<<<(NODES + 255) / 256, 256>>>();
    scan1_kernel<<<SCAN_NB, SCAN_B>>>();
    scan2_kernel<<<1, 32>>>();
    scan3_kernel<<<SCAN_NB, SCAN_B>>>();
    fill_kernel<<<(EDGES + 255) / 256, 256>>>(src, dst);

    // ---- layer 1: h1 = (x @ W1) * deg_inv ; out1 = b1 + sum_in h1 ----
    {
        dim3 grid(HID_C / 64, (NODES + 63) / 64);
        gemm_kernel<HID_C, false><<<grid, 256>>>(x, W1, NODES);
    }
    {
        long long threads = (long long)NODES * 32;
        agg128_kernel<<<(unsigned)((threads + 255) / 256), 256>>>(b1);
    }

    // ---- layer 2: h2 = (relu(out1) @ W2) * deg_inv ; out = b2 + sum_in h2 ----
    {
        dim3 grid(OUT_C / 64, (NODES + 63) / 64);
        gemm_kernel<OUT_C, true><<<grid, 256>>>(nullptr, W2, NODES);
    }
    {
        long long threads = (long long)NODES * 16;
        agg64_kernel<<<(unsigned)((threads + 255) / 256), 256>>>(b2, outp);
    }
}

// round 11
// speedup vs baseline: 1.7890x; 1.1156x over previous
#include <cuda_runtime.h>
#include <cuda_bf16.h>
#include <cstdint>

// Problem constants (fixed by the reference)
#define NODES 100000
#define EDGES 1600000
#define IN_C  128
#define HID_C 128
#define OUT_C 64

#define SCAN_B 1024
#define SCAN_NB ((NODES + SCAN_B - 1) / SCAN_B)   // 98

// -------- scratch (no allocation allowed -> __device__ globals) --------
__device__ int   g_odeg[NODES];          // out-degree (src histogram)
__device__ float g_deginv[NODES];
__device__ int   g_cnt[NODES];           // in-degree (dst histogram)
__device__ int   g_off[NODES + 1];       // CSR offsets (by dst)
__device__ int   g_cur[NODES];           // fill cursors
__device__ int   g_csr[EDGES];           // src ids grouped by dst
__device__ int   g_bsum[SCAN_NB + 1];    // scan block sums
__device__ float g_h1[NODES * HID_C];    // scaled projection, layer 1
__device__ float g_out1[NODES * HID_C];  // relu input (aggregated + b1)
__device__ float g_h2[NODES * OUT_C];    // scaled projection, layer 2

// -------- init: zero both histograms --------
__global__ void init_kernel() {
    int i = blockIdx.x * blockDim.x + threadIdx.x;
    if (i < NODES) { g_odeg[i] = 0; g_cnt[i] = 0; }
}

// -------- histograms: out-degree of src, in-degree of dst --------
__global__ void hist_kernel(const int* __restrict__ src,
                            const int* __restrict__ dst) {
    int i = blockIdx.x * blockDim.x + threadIdx.x;
    if (i < EDGES) {
        atomicAdd(&g_odeg[src[i]], 1);
        atomicAdd(&g_cnt[dst[i]], 1);
    }
}

__global__ void deginv_kernel() {
    int i = blockIdx.x * blockDim.x + threadIdx.x;
    if (i < NODES) g_deginv[i] = 1.0f / fmaxf((float)g_odeg[i], 1.0f);
}

// -------- 3-kernel exclusive scan of g_cnt -> g_off --------
__global__ __launch_bounds__(SCAN_B) void scan1_kernel() {
    int gi = blockIdx.x * SCAN_B + threadIdx.x;
    int v = (gi < NODES) ? g_cnt[gi] : 0;
    int lane = threadIdx.x & 31, w = threadIdx.x >> 5;
    int x = v;
#pragma unroll
    for (int o = 1; o < 32; o <<= 1) {
        int y = __shfl_up_sync(0xffffffffu, x, o);
        if (lane >= o) x += y;
    }
    __shared__ int wsum[32];
    if (lane == 31) wsum[w] = x;
    __syncthreads();
    if (w == 0) {
        int s = wsum[lane];
#pragma unroll
        for (int o = 1; o < 32; o <<= 1) {
            int y = __shfl_up_sync(0xffffffffu, s, o);
            if (lane >= o) s += y;
        }
        wsum[lane] = s;
    }
    __syncthreads();
    int incl = x + (w > 0 ? wsum[w - 1] : 0);
    if (gi < NODES) g_off[gi] = incl - v;           // block-local exclusive
    if (threadIdx.x == SCAN_B - 1) g_bsum[blockIdx.x] = incl;
}

__global__ void scan2_kernel() {
    if (threadIdx.x == 0) {
        int run = 0;
        for (int b = 0; b < SCAN_NB; b++) {
            int t = g_bsum[b];
            g_bsum[b] = run;
            run += t;
        }
    }
}

__global__ __launch_bounds__(SCAN_B) void scan3_kernel() {
    int gi = blockIdx.x * SCAN_B + threadIdx.x;
    if (gi < NODES) {
        int o = g_off[gi] + g_bsum[blockIdx.x];
        g_off[gi] = o;
        g_cur[gi] = o;
    }
    if (gi == 0) g_off[NODES] = EDGES;
}

// -------- CSR fill: bucket src ids by dst --------
__global__ void fill_kernel(const int* __restrict__ src,
                            const int* __restrict__ dst) {
    int i = blockIdx.x * blockDim.x + threadIdx.x;
    if (i < EDGES) {
        int p = atomicAdd(&g_cur[dst[i]], 1);
        g_csr[p] = src[i];
    }
}

// ===================== TF32 tensor-core GEMM =====================
// C[M,NOUT] = op(A[M,128]) @ B[128,NOUT], scaled by deg_inv[row].
// 3-term split precision: a = ah + al (tf32 hi + residual),
// D += ah*bh + ah*bl + al*bh  ->  ~eps^2 (2.4e-7) accuracy.
// Tile: BM=128, BN=64, KC=32. 256 threads = 8 warps; warp = 16 rows x 64 cols.

__device__ __forceinline__ uint32_t tf32_hi_bits(float x) {
    uint32_t r;
    asm("cvt.rna.tf32.f32 %0, %1;" : "=r"(r) : "f"(x));
    return r;
}

__device__ __forceinline__ void mma_tf32(float c[4],
                                         uint32_t a0, uint32_t a1, uint32_t a2, uint32_t a3,
                                         uint32_t b0, uint32_t b1) {
    asm volatile(
        "mma.sync.aligned.m16n8k8.row.col.f32.tf32.tf32.f32 "
        "{%0,%1,%2,%3}, {%4,%5,%6,%7}, {%8,%9}, {%0,%1,%2,%3};\n"
        : "+f"(c[0]), "+f"(c[1]), "+f"(c[2]), "+f"(c[3])
        : "r"(a0), "r"(a1), "r"(a2), "r"(a3), "r"(b0), "r"(b1));
}

template <int NOUT, bool SECOND>
__global__ __launch_bounds__(256) void gemm_tc_kernel(const float* __restrict__ Ain,
                                                      const float* __restrict__ B,
                                                      int M) {
    constexpr int BM = 128, BN = 64, KC = 32;
    constexpr int APITCH = KC + 4;   // 36: bank(g,t) = 4g+t  (injective over warp)
    constexpr int BPITCH = BN + 8;   // 72: bank(t,g) = 8t+g  (injective over warp)

    const float* A = SECOND ? g_out1 : Ain;
    float*       C = SECOND ? g_h2   : g_h1;

    __shared__ float As[BM * APITCH];   // 18 KB
    __shared__ float Bs[KC * BPITCH];   //  9 KB

    const int tid  = threadIdx.x;
    const int lane = tid & 31;
    const int wid  = tid >> 5;
    const int rowBase = blockIdx.y * BM;
    const int colBase = blockIdx.x * BN;
    const int wrow = wid * 16;

    const int g = lane >> 2;     // group id 0..7
    const int t = lane & 3;      // thread-in-group 0..3

    float c[8][4];
#pragma unroll
    for (int nt = 0; nt < 8; nt++)
#pragma unroll
        for (int j = 0; j < 4; j++) c[nt][j] = 0.0f;

    for (int k0 = 0; k0 < 128; k0 += KC) {
        // ---- load A tile: BM x KC (float4 per thread x 4 iters) ----
#pragma unroll
        for (int i = tid; i < BM * KC / 4; i += 256) {
            int r = i >> 3;              // KC/4 = 8 quads per row
            int q = i & 7;
            int grow = rowBase + r;
            float4 a = make_float4(0.f, 0.f, 0.f, 0.f);
            if (grow < M)
                a = *reinterpret_cast<const float4*>(A + (size_t)grow * 128 + k0 + q * 4);
            if (SECOND) {
                a.x = fmaxf(a.x, 0.f); a.y = fmaxf(a.y, 0.f);
                a.z = fmaxf(a.z, 0.f); a.w = fmaxf(a.w, 0.f);
            }
            *reinterpret_cast<float4*>(&As[r * APITCH + q * 4]) = a;
        }
        // ---- load B tile: KC x BN ----
#pragma unroll
        for (int i = tid; i < KC * BN / 4; i += 256) {
            int r = i / (BN / 4);
            int q = i % (BN / 4);
            float4 b = *reinterpret_cast<const float4*>(B + (size_t)(k0 + r) * NOUT + colBase + q * 4);
            *reinterpret_cast<float4*>(&Bs[r * BPITCH + q * 4]) = b;
        }
        __syncthreads();

#pragma unroll
        for (int kk = 0; kk < KC; kk += 8) {
            // A fragment (row-major m16k8)
            float fa0 = As[(wrow + g)     * APITCH + kk + t];
            float fa1 = As[(wrow + g + 8) * APITCH + kk + t];
            float fa2 = As[(wrow + g)     * APITCH + kk + t + 4];
            float fa3 = As[(wrow + g + 8) * APITCH + kk + t + 4];
            uint32_t ah0 = tf32_hi_bits(fa0), ah1 = tf32_hi_bits(fa1);
            uint32_t ah2 = tf32_hi_bits(fa2), ah3 = tf32_hi_bits(fa3);
            uint32_t al0 = __float_as_uint(fa0 - __uint_as_float(ah0));
            uint32_t al1 = __float_as_uint(fa1 - __uint_as_float(ah1));
            uint32_t al2 = __float_as_uint(fa2 - __uint_as_float(ah2));
            uint32_t al3 = __float_as_uint(fa3 - __uint_as_float(ah3));

#pragma unroll
            for (int nt = 0; nt < 8; nt++) {
                float fb0 = Bs[(kk + t)     * BPITCH + nt * 8 + g];
                float fb1 = Bs[(kk + t + 4) * BPITCH + nt * 8 + g];
                uint32_t bh0 = tf32_hi_bits(fb0), bh1 = tf32_hi_bits(fb1);
                uint32_t bl0 = __float_as_uint(fb0 - __uint_as_float(bh0));
                uint32_t bl1 = __float_as_uint(fb1 - __uint_as_float(bh1));
                mma_tf32(c[nt], ah0, ah1, ah2, ah3, bh0, bh1);   // hi*hi
                mma_tf32(c[nt], ah0, ah1, ah2, ah3, bl0, bl1);   // hi*lo
                mma_tf32(c[nt], al0, al1, al2, al3, bh0, bh1);   // lo*hi
            }
        }
        __syncthreads();
    }

    // ---- epilogue: scale by deg_inv[row], store ----
    int r0 = rowBase + wrow + g;
    int r1 = r0 + 8;
    float s0 = (r0 < M) ? g_deginv[r0] : 0.f;
    float s1 = (r1 < M) ? g_deginv[r1] : 0.f;
#pragma unroll
    for (int nt = 0; nt < 8; nt++) {
        int col = colBase + nt * 8 + 2 * t;
        if (r0 < M) {
            float2 o = make_float2(c[nt][0] * s0, c[nt][1] * s0);
            *reinterpret_cast<float2*>(C + (size_t)r0 * NOUT + col) = o;
        }
        if (r1 < M) {
            float2 o = make_float2(c[nt][2] * s1, c[nt][3] * s1);
            *reinterpret_cast<float2*>(C + (size_t)r1 * NOUT + col) = o;
        }
    }
}

// -------- layer-1 aggregate: warp per dst node, 32 x float4 = 128 ch ------
// 4-wide edge unroll -> 4 independent row loads in flight per lane (MLP=4).
__global__ __launch_bounds__(256) void agg128_kernel(const float* __restrict__ b1) {
    int gw = (blockIdx.x * blockDim.x + threadIdx.x) >> 5;
    int lane = threadIdx.x & 31;
    if (gw >= NODES) return;
    int beg = g_off[gw], end = g_off[gw + 1];
    const float4* __restrict__ H = reinterpret_cast<const float4*>(g_h1);

    float4 a0 = make_float4(0.f, 0.f, 0.f, 0.f);
    float4 a1 = make_float4(0.f, 0.f, 0.f, 0.f);
    float4 a2 = make_float4(0.f, 0.f, 0.f, 0.f);
    float4 a3 = make_float4(0.f, 0.f, 0.f, 0.f);
    int e = beg;
    for (; e + 3 < end; e += 4) {
        int s0 = g_csr[e];
        int s1 = g_csr[e + 1];
        int s2 = g_csr[e + 2];
        int s3 = g_csr[e + 3];
        float4 v0 = H[s0 * 32 + lane];
        float4 v1 = H[s1 * 32 + lane];
        float4 v2 = H[s2 * 32 + lane];
        float4 v3 = H[s3 * 32 + lane];
        a0.x += v0.x; a0.y += v0.y; a0.z += v0.z; a0.w += v0.w;
        a1.x += v1.x; a1.y += v1.y; a1.z += v1.z; a1.w += v1.w;
        a2.x += v2.x; a2.y += v2.y; a2.z += v2.z; a2.w += v2.w;
        a3.x += v3.x; a3.y += v3.y; a3.z += v3.z; a3.w += v3.w;
    }
    for (; e < end; e++) {
        int s = g_csr[e];
        float4 v = H[s * 32 + lane];
        a0.x += v.x; a0.y += v.y; a0.z += v.z; a0.w += v.w;
    }
    float4 bv = reinterpret_cast<const float4*>(b1)[lane];
    float4 o = make_float4(a0.x + a1.x + a2.x + a3.x + bv.x,
                           a0.y + a1.y + a2.y + a3.y + bv.y,
                           a0.z + a1.z + a2.z + a3.z + bv.z,
                           a0.w + a1.w + a2.w + a3.w + bv.w);
    reinterpret_cast<float4*>(g_out1)[gw * 32 + lane] = o;
}

// -------- layer-2 aggregate: HALF-warp per dst node, 16 x float4 = 64 ch --
__global__ __launch_bounds__(256) void agg64_kernel(const float* __restrict__ b2,
                                                    float* __restrict__ outp) {
    int ghw = (blockIdx.x * blockDim.x + threadIdx.x) >> 4;   // half-warp id
    int lane = threadIdx.x & 15;
    if (ghw >= NODES) return;
    int beg = g_off[ghw], end = g_off[ghw + 1];
    const float4* __restrict__ H = reinterpret_cast<const float4*>(g_h2);

    float4 a0 = make_float4(0.f, 0.f, 0.f, 0.f);
    float4 a1 = make_float4(0.f, 0.f, 0.f, 0.f);
    float4 a2 = make_float4(0.f, 0.f, 0.f, 0.f);
    float4 a3 = make_float4(0.f, 0.f, 0.f, 0.f);
    int e = beg;
    for (; e + 3 < end; e += 4) {
        int s0 = g_csr[e];
        int s1 = g_csr[e + 1];
        int s2 = g_csr[e + 2];
        int s3 = g_csr[e + 3];
        float4 v0 = H[s0 * 16 + lane];
        float4 v1 = H[s1 * 16 + lane];
        float4 v2 = H[s2 * 16 + lane];
        float4 v3 = H[s3 * 16 + lane];
        a0.x += v0.x; a0.y += v0.y; a0.z += v0.z; a0.w += v0.w;
        a1.x += v1.x; a1.y += v1.y; a1.z += v1.z; a1.w += v1.w;
        a2.x += v2.x; a2.y += v2.y; a2.z += v2.z; a2.w += v2.w;
        a3.x += v3.x; a3.y += v3.y; a3.z += v3.z; a3.w += v3.w;
    }
    for (; e < end; e++) {
        int s = g_csr[e];
        float4 v = H[s * 16 + lane];
        a0.x += v.x; a0.y += v.y; a0.z += v.z; a0.w += v.w;
    }
    float4 bv = reinterpret_cast<const float4*>(b2)[lane];
    float4 o = make_float4(a0.x + a1.x + a2.x + a3.x + bv.x,
                           a0.y + a1.y + a2.y + a3.y + bv.y,
                           a0.z + a1.z + a2.z + a3.z + bv.z,
                           a0.w + a1.w + a2.w + a3.w + bv.w);
    reinterpret_cast<float4*>(outp)[ghw * 16 + lane] = o;
}

extern "C" void kernel_launch(void* const* d_in, const int* in_sizes, int n_in,
                              void* d_out, int out_size) {
    const float* x  = (const float*)d_in[0];
    const int*   ei = (const int*)d_in[1];   // [2, E]: src then dst
    const float* W1 = (const float*)d_in[2];
    const float* b1 = (const float*)d_in[3];
    const float* W2 = (const float*)d_in[4];
    const float* b2 = (const float*)d_in[5];
    float* outp = (float*)d_out;

    const int* src = ei;
    const int* dst = ei + EDGES;

    // ---- CSR build (reused by both layers) + out-degree ----
    init_kernel<<<(NODES + 255) / 256, 256>>>();
    hist_kernel<<<(EDGES + 255) / 256, 256>>>(src, dst);
    deginv_kernel<<<(NODES + 255) / 256, 256>>>();
    scan1_kernel<<<SCAN_NB, SCAN_B>>>();
    scan2_kernel<<<1, 32>>>();
    scan3_kernel<<<SCAN_NB, SCAN_B>>>();
    fill_kernel<<<(EDGES + 255) / 256, 256>>>(src, dst);

    // ---- layer 1: h1 = (x @ W1) * deg_inv ; out1 = b1 + sum_in h1 ----
    {
        dim3 grid(HID_C / 64, (NODES + 127) / 128);
        gemm_tc_kernel<HID_C, false><<<grid, 256>>>(x, W1, NODES);
    }
    {
        long long threads = (long long)NODES * 32;
        agg128_kernel<<<(unsigned)((threads + 255) / 256), 256>>>(b1);
    }

    // ---- layer 2: h2 = (relu(out1) @ W2) * deg_inv ; out = b2 + sum_in h2 ----
    {
        dim3 grid(OUT_C / 64, (NODES + 127) / 128);
        gemm_tc_kernel<OUT_C, true><<<grid, 256>>>(nullptr, W2, NODES);
    }
    {
        long long threads = (long long)NODES * 16;
        agg64_kernel<<<(unsigned)((threads + 255) / 256), 256>>>(b2, outp);
    }
}

// round 12
// speedup vs baseline: 1.8614x; 1.0405x over previous
#include <cuda_runtime.h>
#include <cuda_bf16.h>
#include <cstdint>

// Problem constants (fixed by the reference)
#define NODES 100000
#define EDGES 1600000
#define IN_C  128
#define HID_C 128
#define OUT_C 64

#define SCAN_B 1024
#define SCAN_NB ((NODES + SCAN_B - 1) / SCAN_B)   // 98

// -------- scratch (no allocation allowed -> __device__ globals) --------
__device__ int   g_odeg[NODES];          // out-degree (src histogram)
__device__ float g_deginv[NODES];
__device__ int   g_cnt[NODES];           // in-degree (dst histogram)
__device__ int   g_off[NODES + 1];       // CSR offsets (by dst)
__device__ int   g_cur[NODES];           // fill cursors
__device__ int   g_csr[EDGES];           // src ids grouped by dst
__device__ int   g_bsum[SCAN_NB + 1];    // scan block sums
__device__ float g_h1[NODES * HID_C];    // scaled projection, layer 1
__device__ float g_out1[NODES * HID_C];  // relu input (aggregated + b1)
__device__ float g_h2[NODES * OUT_C];    // scaled projection, layer 2
// pre-split weights (tf32 hi + fp32 residual)
__device__ float g_w1h[IN_C * HID_C];
__device__ float g_w1l[IN_C * HID_C];
__device__ float g_w2h[HID_C * OUT_C];
__device__ float g_w2l[HID_C * OUT_C];

// -------- init: zero both histograms --------
__global__ void init_kernel() {
    int i = blockIdx.x * blockDim.x + threadIdx.x;
    if (i < NODES) { g_odeg[i] = 0; g_cnt[i] = 0; }
}

// -------- histograms: out-degree of src, in-degree of dst --------
__global__ void hist_kernel(const int* __restrict__ src,
                            const int* __restrict__ dst) {
    int i = blockIdx.x * blockDim.x + threadIdx.x;
    if (i < EDGES) {
        atomicAdd(&g_odeg[src[i]], 1);
        atomicAdd(&g_cnt[dst[i]], 1);
    }
}

__global__ void deginv_kernel() {
    int i = blockIdx.x * blockDim.x + threadIdx.x;
    if (i < NODES) g_deginv[i] = 1.0f / fmaxf((float)g_odeg[i], 1.0f);
}

// -------- weight split: W -> tf32(W) + residual --------
__device__ __forceinline__ uint32_t tf32_hi_bits(float x) {
    uint32_t r;
    asm("cvt.rna.tf32.f32 %0, %1;" : "=r"(r) : "f"(x));
    return r;
}

__global__ void wsplit_kernel(const float* __restrict__ W1,
                              const float* __restrict__ W2) {
    int i = blockIdx.x * blockDim.x + threadIdx.x;
    if (i < IN_C * HID_C) {
        float w = W1[i];
        float h = __uint_as_float(tf32_hi_bits(w));
        g_w1h[i] = h;
        g_w1l[i] = w - h;
    }
    if (i < HID_C * OUT_C) {
        float w = W2[i];
        float h = __uint_as_float(tf32_hi_bits(w));
        g_w2h[i] = h;
        g_w2l[i] = w - h;
    }
}

// -------- 3-kernel exclusive scan of g_cnt -> g_off --------
__global__ __launch_bounds__(SCAN_B) void scan1_kernel() {
    int gi = blockIdx.x * SCAN_B + threadIdx.x;
    int v = (gi < NODES) ? g_cnt[gi] : 0;
    int lane = threadIdx.x & 31, w = threadIdx.x >> 5;
    int x = v;
#pragma unroll
    for (int o = 1; o < 32; o <<= 1) {
        int y = __shfl_up_sync(0xffffffffu, x, o);
        if (lane >= o) x += y;
    }
    __shared__ int wsum[32];
    if (lane == 31) wsum[w] = x;
    __syncthreads();
    if (w == 0) {
        int s = wsum[lane];
#pragma unroll
        for (int o = 1; o < 32; o <<= 1) {
            int y = __shfl_up_sync(0xffffffffu, s, o);
            if (lane >= o) s += y;
        }
        wsum[lane] = s;
    }
    __syncthreads();
    int incl = x + (w > 0 ? wsum[w - 1] : 0);
    if (gi < NODES) g_off[gi] = incl - v;           // block-local exclusive
    if (threadIdx.x == SCAN_B - 1) g_bsum[blockIdx.x] = incl;
}

__global__ void scan2_kernel() {
    if (threadIdx.x == 0) {
        int run = 0;
        for (int b = 0; b < SCAN_NB; b++) {
            int t = g_bsum[b];
            g_bsum[b] = run;
            run += t;
        }
    }
}

__global__ __launch_bounds__(SCAN_B) void scan3_kernel() {
    int gi = blockIdx.x * SCAN_B + threadIdx.x;
    if (gi < NODES) {
        int o = g_off[gi] + g_bsum[blockIdx.x];
        g_off[gi] = o;
        g_cur[gi] = o;
    }
    if (gi == 0) g_off[NODES] = EDGES;
}

// -------- CSR fill: bucket src ids by dst --------
__global__ void fill_kernel(const int* __restrict__ src,
                            const int* __restrict__ dst) {
    int i = blockIdx.x * blockDim.x + threadIdx.x;
    if (i < EDGES) {
        int p = atomicAdd(&g_cur[dst[i]], 1);
        g_csr[p] = src[i];
    }
}

// ===================== TF32 tensor-core GEMM =====================
// C[M,NOUT] = op(A[M,128]) @ B[128,NOUT], scaled by deg_inv[row].
// 3-term split precision with B pre-split (Bh/Bl from global):
// D += ah*bh + ah*bl + al*bh  ->  ~eps^2 accuracy.
// Tile: BM=128, BN=64, KC=32. 256 threads = 8 warps; warp = 16 rows x 64 cols.

__device__ __forceinline__ void mma_tf32(float c[4],
                                         uint32_t a0, uint32_t a1, uint32_t a2, uint32_t a3,
                                         uint32_t b0, uint32_t b1) {
    asm volatile(
        "mma.sync.aligned.m16n8k8.row.col.f32.tf32.tf32.f32 "
        "{%0,%1,%2,%3}, {%4,%5,%6,%7}, {%8,%9}, {%0,%1,%2,%3};\n"
        : "+f"(c[0]), "+f"(c[1]), "+f"(c[2]), "+f"(c[3])
        : "r"(a0), "r"(a1), "r"(a2), "r"(a3), "r"(b0), "r"(b1));
}

template <int NOUT, bool SECOND>
__global__ __launch_bounds__(256) void gemm_tc_kernel(const float* __restrict__ Ain,
                                                      const float* __restrict__ Bh,
                                                      const float* __restrict__ Bl,
                                                      int M) {
    constexpr int BM = 128, BN = 64, KC = 32;
    constexpr int APITCH = KC + 4;   // 36: bank(g,t) = 4g+t  (injective over warp)
    constexpr int BPITCH = BN + 8;   // 72: bank(t,g) = 8t+g  (injective over warp)

    const float* A = SECOND ? g_out1 : Ain;
    float*       C = SECOND ? g_h2   : g_h1;

    __shared__ float As [BM * APITCH];   // 18 KB
    __shared__ float Bsh[KC * BPITCH];   //  9 KB
    __shared__ float Bsl[KC * BPITCH];   //  9 KB

    const int tid  = threadIdx.x;
    const int lane = tid & 31;
    const int wid  = tid >> 5;
    const int rowBase = blockIdx.y * BM;
    const int colBase = blockIdx.x * BN;
    const int wrow = wid * 16;

    const int g = lane >> 2;     // group id 0..7
    const int t = lane & 3;      // thread-in-group 0..3

    float c[8][4];
#pragma unroll
    for (int nt = 0; nt < 8; nt++)
#pragma unroll
        for (int j = 0; j < 4; j++) c[nt][j] = 0.0f;

    for (int k0 = 0; k0 < 128; k0 += KC) {
        // ---- load A tile: BM x KC ----
#pragma unroll
        for (int i = tid; i < BM * KC / 4; i += 256) {
            int r = i >> 3;              // KC/4 = 8 quads per row
            int q = i & 7;
            int grow = rowBase + r;
            float4 a = make_float4(0.f, 0.f, 0.f, 0.f);
            if (grow < M)
                a = *reinterpret_cast<const float4*>(A + (size_t)grow * 128 + k0 + q * 4);
            if (SECOND) {
                a.x = fmaxf(a.x, 0.f); a.y = fmaxf(a.y, 0.f);
                a.z = fmaxf(a.z, 0.f); a.w = fmaxf(a.w, 0.f);
            }
            *reinterpret_cast<float4*>(&As[r * APITCH + q * 4]) = a;
        }
        // ---- load pre-split B tiles: KC x BN each ----
#pragma unroll
        for (int i = tid; i < KC * BN / 4; i += 256) {
            int r = i / (BN / 4);
            int q = i % (BN / 4);
            size_t goff = (size_t)(k0 + r) * NOUT + colBase + q * 4;
            *reinterpret_cast<float4*>(&Bsh[r * BPITCH + q * 4]) =
                *reinterpret_cast<const float4*>(Bh + goff);
            *reinterpret_cast<float4*>(&Bsl[r * BPITCH + q * 4]) =
                *reinterpret_cast<const float4*>(Bl + goff);
        }
        __syncthreads();

#pragma unroll
        for (int kk = 0; kk < KC; kk += 8) {
            // A fragment (row-major m16k8), split in registers
            float fa0 = As[(wrow + g)     * APITCH + kk + t];
            float fa1 = As[(wrow + g + 8) * APITCH + kk + t];
            float fa2 = As[(wrow + g)     * APITCH + kk + t + 4];
            float fa3 = As[(wrow + g + 8) * APITCH + kk + t + 4];
            uint32_t ah0 = tf32_hi_bits(fa0), ah1 = tf32_hi_bits(fa1);
            uint32_t ah2 = tf32_hi_bits(fa2), ah3 = tf32_hi_bits(fa3);
            uint32_t al0 = __float_as_uint(fa0 - __uint_as_float(ah0));
            uint32_t al1 = __float_as_uint(fa1 - __uint_as_float(ah1));
            uint32_t al2 = __float_as_uint(fa2 - __uint_as_float(ah2));
            uint32_t al3 = __float_as_uint(fa3 - __uint_as_float(ah3));

#pragma unroll
            for (int nt = 0; nt < 8; nt++) {
                uint32_t bh0 = __float_as_uint(Bsh[(kk + t)     * BPITCH + nt * 8 + g]);
                uint32_t bh1 = __float_as_uint(Bsh[(kk + t + 4) * BPITCH + nt * 8 + g]);
                uint32_t bl0 = __float_as_uint(Bsl[(kk + t)     * BPITCH + nt * 8 + g]);
                uint32_t bl1 = __float_as_uint(Bsl[(kk + t + 4) * BPITCH + nt * 8 + g]);
                mma_tf32(c[nt], ah0, ah1, ah2, ah3, bh0, bh1);   // hi*hi
                mma_tf32(c[nt], ah0, ah1, ah2, ah3, bl0, bl1);   // hi*lo
                mma_tf32(c[nt], al0, al1, al2, al3, bh0, bh1);   // lo*hi
            }
        }
        __syncthreads();
    }

    // ---- epilogue: scale by deg_inv[row], store ----
    int r0 = rowBase + wrow + g;
    int r1 = r0 + 8;
    float s0 = (r0 < M) ? g_deginv[r0] : 0.f;
    float s1 = (r1 < M) ? g_deginv[r1] : 0.f;
#pragma unroll
    for (int nt = 0; nt < 8; nt++) {
        int col = colBase + nt * 8 + 2 * t;
        if (r0 < M) {
            float2 o = make_float2(c[nt][0] * s0, c[nt][1] * s0);
            *reinterpret_cast<float2*>(C + (size_t)r0 * NOUT + col) = o;
        }
        if (r1 < M) {
            float2 o = make_float2(c[nt][2] * s1, c[nt][3] * s1);
            *reinterpret_cast<float2*>(C + (size_t)r1 * NOUT + col) = o;
        }
    }
}

// -------- layer-1 aggregate: warp per dst node, 32 x float4 = 128 ch ------
__global__ __launch_bounds__(256) void agg128_kernel(const float* __restrict__ b1) {
    int gw = (blockIdx.x * blockDim.x + threadIdx.x) >> 5;
    int lane = threadIdx.x & 31;
    if (gw >= NODES) return;
    int beg = g_off[gw], end = g_off[gw + 1];
    const float4* __restrict__ H = reinterpret_cast<const float4*>(g_h1);

    float4 a0 = make_float4(0.f, 0.f, 0.f, 0.f);
    float4 a1 = make_float4(0.f, 0.f, 0.f, 0.f);
    float4 a2 = make_float4(0.f, 0.f, 0.f, 0.f);
    float4 a3 = make_float4(0.f, 0.f, 0.f, 0.f);
    int e = beg;
    for (; e + 3 < end; e += 4) {
        int s0 = g_csr[e];
        int s1 = g_csr[e + 1];
        int s2 = g_csr[e + 2];
        int s3 = g_csr[e + 3];
        float4 v0 = H[s0 * 32 + lane];
        float4 v1 = H[s1 * 32 + lane];
        float4 v2 = H[s2 * 32 + lane];
        float4 v3 = H[s3 * 32 + lane];
        a0.x += v0.x; a0.y += v0.y; a0.z += v0.z; a0.w += v0.w;
        a1.x += v1.x; a1.y += v1.y; a1.z += v1.z; a1.w += v1.w;
        a2.x += v2.x; a2.y += v2.y; a2.z += v2.z; a2.w += v2.w;
        a3.x += v3.x; a3.y += v3.y; a3.z += v3.z; a3.w += v3.w;
    }
    for (; e < end; e++) {
        int s = g_csr[e];
        float4 v = H[s * 32 + lane];
        a0.x += v.x; a0.y += v.y; a0.z += v.z; a0.w += v.w;
    }
    float4 bv = reinterpret_cast<const float4*>(b1)[lane];
    float4 o = make_float4(a0.x + a1.x + a2.x + a3.x + bv.x,
                           a0.y + a1.y + a2.y + a3.y + bv.y,
                           a0.z + a1.z + a2.z + a3.z + bv.z,
                           a0.w + a1.w + a2.w + a3.w + bv.w);
    reinterpret_cast<float4*>(g_out1)[gw * 32 + lane] = o;
}

// -------- layer-2 aggregate: HALF-warp per dst node, 16 x float4 = 64 ch --
__global__ __launch_bounds__(256) void agg64_kernel(const float* __restrict__ b2,
                                                    float* __restrict__ outp) {
    int ghw = (blockIdx.x * blockDim.x + threadIdx.x) >> 4;   // half-warp id
    int lane = threadIdx.x & 15;
    if (ghw >= NODES) return;
    int beg = g_off[ghw], end = g_off[ghw + 1];
    const float4* __restrict__ H = reinterpret_cast<const float4*>(g_h2);

    float4 a0 = make_float4(0.f, 0.f, 0.f, 0.f);
    float4 a1 = make_float4(0.f, 0.f, 0.f, 0.f);
    float4 a2 = make_float4(0.f, 0.f, 0.f, 0.f);
    float4 a3 = make_float4(0.f, 0.f, 0.f, 0.f);
    int e = beg;
    for (; e + 3 < end; e += 4) {
        int s0 = g_csr[e];
        int s1 = g_csr[e + 1];
        int s2 = g_csr[e + 2];
        int s3 = g_csr[e + 3];
        float4 v0 = H[s0 * 16 + lane];
        float4 v1 = H[s1 * 16 + lane];
        float4 v2 = H[s2 * 16 + lane];
        float4 v3 = H[s3 * 16 + lane];
        a0.x += v0.x; a0.y += v0.y; a0.z += v0.z; a0.w += v0.w;
        a1.x += v1.x; a1.y += v1.y; a1.z += v1.z; a1.w += v1.w;
        a2.x += v2.x; a2.y += v2.y; a2.z += v2.z; a2.w += v2.w;
        a3.x += v3.x; a3.y += v3.y; a3.z += v3.z; a3.w += v3.w;
    }
    for (; e < end; e++) {
        int s = g_csr[e];
        float4 v = H[s * 16 + lane];
        a0.x += v.x; a0.y += v.y; a0.z += v.z; a0.w += v.w;
    }
    float4 bv = reinterpret_cast<const float4*>(b2)[lane];
    float4 o = make_float4(a0.x + a1.x + a2.x + a3.x + bv.x,
                           a0.y + a1.y + a2.y + a3.y + bv.y,
                           a0.z + a1.z + a2.z + a3.z + bv.z,
                           a0.w + a1.w + a2.w + a3.w + bv.w);
    reinterpret_cast<float4*>(outp)[ghw * 16 + lane] = o;
}

extern "C" void kernel_launch(void* const* d_in, const int* in_sizes, int n_in,
                              void* d_out, int out_size) {
    const float* x  = (const float*)d_in[0];
    const int*   ei = (const int*)d_in[1];   // [2, E]: src then dst
    const float* W1 = (const float*)d_in[2];
    const float* b1 = (const float*)d_in[3];
    const float* W2 = (const float*)d_in[4];
    const float* b2 = (const float*)d_in[5];
    float* outp = (float*)d_out;

    const int* src = ei;
    const int* dst = ei + EDGES;

    // resolve device-global addresses for the pre-split weights
    float *w1h, *w1l, *w2h, *w2l;
    cudaGetSymbolAddress((void**)&w1h, g_w1h);
    cudaGetSymbolAddress((void**)&w1l, g_w1l);
    cudaGetSymbolAddress((void**)&w2h, g_w2h);
    cudaGetSymbolAddress((void**)&w2l, g_w2l);

    // ---- CSR build (reused by both layers) + out-degree + weight split ----
    init_kernel<<<(NODES + 255) / 256, 256>>>();
    wsplit_kernel<<<(IN_C * HID_C + 255) / 256, 256>>>(W1, W2);
    hist_kernel<<<(EDGES + 255) / 256, 256>>>(src, dst);
    deginv_kernel<<<(NODES + 255) / 256, 256>>>();
    scan1_kernel<<<SCAN_NB, SCAN_B>>>();
    scan2_kernel<<<1, 32>>>();
    scan3_kernel<<<SCAN_NB, SCAN_B>>>();
    fill_kernel<<<(EDGES + 255) / 256, 256>>>(src, dst);

    // ---- layer 1: h1 = (x @ W1) * deg_inv ; out1 = b1 + sum_in h1 ----
    {
        dim3 grid(HID_C / 64, (NODES + 127) / 128);
        gemm_tc_kernel<HID_C, false><<<grid, 256>>>(x, w1h, w1l, NODES);
    }
    {
        long long threads = (long long)NODES * 32;
        agg128_kernel<<<(unsigned)((threads + 255) / 256), 256>>>(b1);
    }

    // ---- layer 2: h2 = (relu(out1) @ W2) * deg_inv ; out = b2 + sum_in h2 ----
    {
        dim3 grid(OUT_C / 64, (NODES + 127) / 128);
        gemm_tc_kernel<OUT_C, true><<<grid, 256>>>(nullptr, w2h, w2l, NODES);
    }
    {
        long long threads = (long long)NODES * 16;
        agg64_kernel<<<(unsigned)((threads + 255) / 256), 256>>>(b2, outp);
    }
}

// round 13
// speedup vs baseline: 2.0752x; 1.1148x over previous
#include <cuda_runtime.h>
#include <cuda_bf16.h>
#include <cstdint>

// Problem constants (fixed by the reference)
#define NODES 100000
#define EDGES 1600000
#define IN_C  128
#define HID_C 128
#define OUT_C 64

#define SCAN_B 1024
#define SCAN_NB ((NODES + SCAN_B - 1) / SCAN_B)   // 98

// -------- scratch (no allocation allowed -> __device__ globals) --------
__device__ int   g_odeg[NODES];          // out-degree (src histogram)
__device__ float g_deginv[NODES];
__device__ int   g_cnt[NODES];           // in-degree (dst histogram)
__device__ int   g_off[NODES + 1];       // CSR offsets (by dst)
__device__ int   g_cur[NODES];           // fill cursors
__device__ int   g_csr[EDGES];           // src ids grouped by dst
__device__ int   g_bsum[SCAN_NB + 1];    // scan block sums
__device__ float g_h1[NODES * HID_C];    // scaled projection, layer 1
__device__ float g_out1[NODES * HID_C];  // relu input (aggregated + b1)
__device__ float g_h2[NODES * OUT_C];    // scaled projection, layer 2
// pre-split, k-pair-packed weights: [K/2][N] of uint32 {lo=bf16(W[2k]), hi=bf16(W[2k+1])}
__device__ uint32_t g_w1h[(IN_C / 2) * HID_C];
__device__ uint32_t g_w1l[(IN_C / 2) * HID_C];
__device__ uint32_t g_w2h[(HID_C / 2) * OUT_C];
__device__ uint32_t g_w2l[(HID_C / 2) * OUT_C];

// -------- histograms: out-degree of src, in-degree of dst --------
__global__ void hist_kernel(const int* __restrict__ src,
                            const int* __restrict__ dst) {
    int i = blockIdx.x * blockDim.x + threadIdx.x;
    if (i < EDGES) {
        atomicAdd(&g_odeg[src[i]], 1);
        atomicAdd(&g_cnt[dst[i]], 1);
    }
}

// -------- weight split: W -> bf16 hi + bf16 residual, k-pair packed --------
__device__ __forceinline__ uint32_t pack_bf16_pair(float x0, float x1) {
    // lo half = bf16(x0), hi half = bf16(x1)
    uint32_t r;
    asm("cvt.rn.bf16x2.f32 %0, %1, %2;" : "=r"(r) : "f"(x1), "f"(x0));
    return r;
}

__global__ void wsplit_kernel(const float* __restrict__ W1,
                              const float* __restrict__ W2) {
    int i = blockIdx.x * blockDim.x + threadIdx.x;
    if (i < (IN_C / 2) * HID_C) {
        int kp = i / HID_C, n = i % HID_C;
        float w0 = W1[(2 * kp) * HID_C + n];
        float w1 = W1[(2 * kp + 1) * HID_C + n];
        uint32_t h = pack_bf16_pair(w0, w1);
        float h0 = __uint_as_float(h << 16);
        float h1 = __uint_as_float(h & 0xFFFF0000u);
        g_w1h[i] = h;
        g_w1l[i] = pack_bf16_pair(w0 - h0, w1 - h1);
    }
    if (i < (HID_C / 2) * OUT_C) {
        int kp = i / OUT_C, n = i % OUT_C;
        float w0 = W2[(2 * kp) * OUT_C + n];
        float w1 = W2[(2 * kp + 1) * OUT_C + n];
        uint32_t h = pack_bf16_pair(w0, w1);
        float h0 = __uint_as_float(h << 16);
        float h1 = __uint_as_float(h & 0xFFFF0000u);
        g_w2h[i] = h;
        g_w2l[i] = pack_bf16_pair(w0 - h0, w1 - h1);
    }
}

// -------- 3-kernel exclusive scan of g_cnt -> g_off --------
__global__ __launch_bounds__(SCAN_B) void scan1_kernel() {
    int gi = blockIdx.x * SCAN_B + threadIdx.x;
    int v = (gi < NODES) ? g_cnt[gi] : 0;
    int lane = threadIdx.x & 31, w = threadIdx.x >> 5;
    int x = v;
#pragma unroll
    for (int o = 1; o < 32; o <<= 1) {
        int y = __shfl_up_sync(0xffffffffu, x, o);
        if (lane >= o) x += y;
    }
    __shared__ int wsum[32];
    if (lane == 31) wsum[w] = x;
    __syncthreads();
    if (w == 0) {
        int s = wsum[lane];
#pragma unroll
        for (int o = 1; o < 32; o <<= 1) {
            int y = __shfl_up_sync(0xffffffffu, s, o);
            if (lane >= o) s += y;
        }
        wsum[lane] = s;
    }
    __syncthreads();
    int incl = x + (w > 0 ? wsum[w - 1] : 0);
    if (gi < NODES) g_off[gi] = incl - v;           // block-local exclusive
    if (threadIdx.x == SCAN_B - 1) g_bsum[blockIdx.x] = incl;
}

__global__ void scan2_kernel() {
    if (threadIdx.x == 0) {
        int run = 0;
        for (int b = 0; b < SCAN_NB; b++) {
            int t = g_bsum[b];
            g_bsum[b] = run;
            run += t;
        }
    }
}

// scan3 + deg_inv fused
__global__ __launch_bounds__(SCAN_B) void scan3_kernel() {
    int gi = blockIdx.x * SCAN_B + threadIdx.x;
    if (gi < NODES) {
        int o = g_off[gi] + g_bsum[blockIdx.x];
        g_off[gi] = o;
        g_cur[gi] = o;
        g_deginv[gi] = 1.0f / fmaxf((float)g_odeg[gi], 1.0f);
    }
    if (gi == 0) g_off[NODES] = EDGES;
}

// -------- CSR fill: bucket src ids by dst --------
__global__ void fill_kernel(const int* __restrict__ src,
                            const int* __restrict__ dst) {
    int i = blockIdx.x * blockDim.x + threadIdx.x;
    if (i < EDGES) {
        int p = atomicAdd(&g_cur[dst[i]], 1);
        g_csr[p] = src[i];
    }
}

// ===================== split-BF16 tensor-core GEMM =====================
// C[M,NOUT] = op(A[M,128]) @ B[128,NOUT], scaled by deg_inv[row].
// a = ah + al (bf16 hi + bf16 residual); B pre-split the same way.
// D += ah*bh + ah*bl + al*bh  ->  ~eps_bf16^2 (1.5e-5) accuracy.
// mma.m16n8k16.bf16: half the mma + half the B-LDS vs the tf32 path.
// Tile: BM=128, BN=64, KC=32. 256 threads = 8 warps; warp = 16 rows x 64 cols.

__device__ __forceinline__ void mma_bf16(float c[4],
                                         uint32_t a0, uint32_t a1, uint32_t a2, uint32_t a3,
                                         uint32_t b0, uint32_t b1) {
    asm volatile(
        "mma.sync.aligned.m16n8k16.row.col.f32.bf16.bf16.f32 "
        "{%0,%1,%2,%3}, {%4,%5,%6,%7}, {%8,%9}, {%0,%1,%2,%3};\n"
        : "+f"(c[0]), "+f"(c[1]), "+f"(c[2]), "+f"(c[3])
        : "r"(a0), "r"(a1), "r"(a2), "r"(a3), "r"(b0), "r"(b1));
}

// split a fp32 pair into bf16x2 hi + bf16x2 residual
__device__ __forceinline__ void split_pair(float x0, float x1,
                                           uint32_t& h, uint32_t& l) {
    h = pack_bf16_pair(x0, x1);
    float h0 = __uint_as_float(h << 16);          // bf16 -> f32 is a shift
    float h1 = __uint_as_float(h & 0xFFFF0000u);
    l = pack_bf16_pair(x0 - h0, x1 - h1);
}

template <int NOUT, bool SECOND>
__global__ __launch_bounds__(256) void gemm_tc_kernel(const float* __restrict__ Ain,
                                                      const uint32_t* __restrict__ Bh,
                                                      const uint32_t* __restrict__ Bl,
                                                      int M) {
    constexpr int BM = 128, BN = 64, KC = 32;
    constexpr int APITCH = 40;   // fp32 words; conflict-free 64-bit frag loads
    constexpr int BPITCH = 72;   // uint32 words; bank = 8t+g (injective)

    const float* A = SECOND ? g_out1 : Ain;
    float*       C = SECOND ? g_h2   : g_h1;

    __shared__ float    As [BM * APITCH];           // 20 KB
    __shared__ uint32_t Bsh[(KC / 2) * BPITCH];     // 4.5 KB
    __shared__ uint32_t Bsl[(KC / 2) * BPITCH];     // 4.5 KB

    const int tid  = threadIdx.x;
    const int lane = tid & 31;
    const int wid  = tid >> 5;
    const int rowBase = blockIdx.y * BM;
    const int colBase = blockIdx.x * BN;
    const int wrow = wid * 16;

    const int g = lane >> 2;     // group id 0..7
    const int t = lane & 3;      // thread-in-group 0..3

    float c[8][4];
#pragma unroll
    for (int nt = 0; nt < 8; nt++)
#pragma unroll
        for (int j = 0; j < 4; j++) c[nt][j] = 0.0f;

    for (int k0 = 0; k0 < 128; k0 += KC) {
        // ---- load A tile: BM x KC fp32 ----
#pragma unroll
        for (int i = tid; i < BM * KC / 4; i += 256) {
            int r = i >> 3;              // KC/4 = 8 quads per row
            int q = i & 7;
            int grow = rowBase + r;
            float4 a = make_float4(0.f, 0.f, 0.f, 0.f);
            if (grow < M)
                a = *reinterpret_cast<const float4*>(A + (size_t)grow * 128 + k0 + q * 4);
            if (SECOND) {
                a.x = fmaxf(a.x, 0.f); a.y = fmaxf(a.y, 0.f);
                a.z = fmaxf(a.z, 0.f); a.w = fmaxf(a.w, 0.f);
            }
            *reinterpret_cast<float4*>(&As[r * APITCH + q * 4]) = a;
        }
        // ---- load packed B tiles: (KC/2) x BN uint32, layout [kp][n] ----
        {
            int kp = tid >> 4;           // 0..15
            int nq = tid & 15;           // 0..15 (x4 cols)
            size_t goff = (size_t)(k0 / 2 + kp) * NOUT + colBase + nq * 4;
            *reinterpret_cast<uint4*>(&Bsh[kp * BPITCH + nq * 4]) =
                *reinterpret_cast<const uint4*>(Bh + goff);
            *reinterpret_cast<uint4*>(&Bsl[kp * BPITCH + nq * 4]) =
                *reinterpret_cast<const uint4*>(Bl + goff);
        }
        __syncthreads();

#pragma unroll
        for (int kk = 0; kk < KC; kk += 16) {
            // A fragment (row-major m16k16): 4 fp32 pairs -> split in regs
            float2 p0 = *reinterpret_cast<const float2*>(&As[(wrow + g)     * APITCH + kk + 2 * t]);
            float2 p1 = *reinterpret_cast<const float2*>(&As[(wrow + g + 8) * APITCH + kk + 2 * t]);
            float2 p2 = *reinterpret_cast<const float2*>(&As[(wrow + g)     * APITCH + kk + 2 * t + 8]);
            float2 p3 = *reinterpret_cast<const float2*>(&As[(wrow + g + 8) * APITCH + kk + 2 * t + 8]);
            uint32_t ah0, al0, ah1, al1, ah2, al2, ah3, al3;
            split_pair(p0.x, p0.y, ah0, al0);
            split_pair(p1.x, p1.y, ah1, al1);
            split_pair(p2.x, p2.y, ah2, al2);
            split_pair(p3.x, p3.y, ah3, al3);

            const int kb = kk / 2;       // 0 or 8
#pragma unroll
            for (int nt = 0; nt < 8; nt++) {
                uint32_t bh0 = Bsh[(kb + t)     * BPITCH + nt * 8 + g];
                uint32_t bh1 = Bsh[(kb + t + 4) * BPITCH + nt * 8 + g];
                uint32_t bl0 = Bsl[(kb + t)     * BPITCH + nt * 8 + g];
                uint32_t bl1 = Bsl[(kb + t + 4) * BPITCH + nt * 8 + g];
                mma_bf16(c[nt], ah0, ah1, ah2, ah3, bh0, bh1);   // hi*hi
                mma_bf16(c[nt], ah0, ah1, ah2, ah3, bl0, bl1);   // hi*lo
                mma_bf16(c[nt], al0, al1, al2, al3, bh0, bh1);   // lo*hi
            }
        }
        __syncthreads();
    }

    // ---- epilogue: scale by deg_inv[row], store ----
    int r0 = rowBase + wrow + g;
    int r1 = r0 + 8;
    float s0 = (r0 < M) ? g_deginv[r0] : 0.f;
    float s1 = (r1 < M) ? g_deginv[r1] : 0.f;
#pragma unroll
    for (int nt = 0; nt < 8; nt++) {
        int col = colBase + nt * 8 + 2 * t;
        if (r0 < M) {
            float2 o = make_float2(c[nt][0] * s0, c[nt][1] * s0);
            *reinterpret_cast<float2*>(C + (size_t)r0 * NOUT + col) = o;
        }
        if (r1 < M) {
            float2 o = make_float2(c[nt][2] * s1, c[nt][3] * s1);
            *reinterpret_cast<float2*>(C + (size_t)r1 * NOUT + col) = o;
        }
    }
}

// -------- layer-1 aggregate: warp per dst node, 32 x float4 = 128 ch ------
__global__ __launch_bounds__(256) void agg128_kernel(const float* __restrict__ b1) {
    int gw = (blockIdx.x * blockDim.x + threadIdx.x) >> 5;
    int lane = threadIdx.x & 31;
    if (gw >= NODES) return;
    int beg = g_off[gw], end = g_off[gw + 1];
    const float4* __restrict__ H = reinterpret_cast<const float4*>(g_h1);

    float4 a0 = make_float4(0.f, 0.f, 0.f, 0.f);
    float4 a1 = make_float4(0.f, 0.f, 0.f, 0.f);
    float4 a2 = make_float4(0.f, 0.f, 0.f, 0.f);
    float4 a3 = make_float4(0.f, 0.f, 0.f, 0.f);
    int e = beg;
    for (; e + 3 < end; e += 4) {
        int s0 = g_csr[e];
        int s1 = g_csr[e + 1];
        int s2 = g_csr[e + 2];
        int s3 = g_csr[e + 3];
        float4 v0 = H[s0 * 32 + lane];
        float4 v1 = H[s1 * 32 + lane];
        float4 v2 = H[s2 * 32 + lane];
        float4 v3 = H[s3 * 32 + lane];
        a0.x += v0.x; a0.y += v0.y; a0.z += v0.z; a0.w += v0.w;
        a1.x += v1.x; a1.y += v1.y; a1.z += v1.z; a1.w += v1.w;
        a2.x += v2.x; a2.y += v2.y; a2.z += v2.z; a2.w += v2.w;
        a3.x += v3.x; a3.y += v3.y; a3.z += v3.z; a3.w += v3.w;
    }
    for (; e < end; e++) {
        int s = g_csr[e];
        float4 v = H[s * 32 + lane];
        a0.x += v.x; a0.y += v.y; a0.z += v.z; a0.w += v.w;
    }
    float4 bv = reinterpret_cast<const float4*>(b1)[lane];
    float4 o = make_float4(a0.x + a1.x + a2.x + a3.x + bv.x,
                           a0.y + a1.y + a2.y + a3.y + bv.y,
                           a0.z + a1.z + a2.z + a3.z + bv.z,
                           a0.w + a1.w + a2.w + a3.w + bv.w);
    reinterpret_cast<float4*>(g_out1)[gw * 32 + lane] = o;
}

// -------- layer-2 aggregate: HALF-warp per dst node, 16 x float4 = 64 ch --
__global__ __launch_bounds__(256) void agg64_kernel(const float* __restrict__ b2,
                                                    float* __restrict__ outp) {
    int ghw = (blockIdx.x * blockDim.x + threadIdx.x) >> 4;   // half-warp id
    int lane = threadIdx.x & 15;
    if (ghw >= NODES) return;
    int beg = g_off[ghw], end = g_off[ghw + 1];
    const float4* __restrict__ H = reinterpret_cast<const float4*>(g_h2);

    float4 a0 = make_float4(0.f, 0.f, 0.f, 0.f);
    float4 a1 = make_float4(0.f, 0.f, 0.f, 0.f);
    float4 a2 = make_float4(0.f, 0.f, 0.f, 0.f);
    float4 a3 = make_float4(0.f, 0.f, 0.f, 0.f);
    int e = beg;
    for (; e + 3 < end; e += 4) {
        int s0 = g_csr[e];
        int s1 = g_csr[e + 1];
        int s2 = g_csr[e + 2];
        int s3 = g_csr[e + 3];
        float4 v0 = H[s0 * 16 + lane];
        float4 v1 = H[s1 * 16 + lane];
        float4 v2 = H[s2 * 16 + lane];
        float4 v3 = H[s3 * 16 + lane];
        a0.x += v0.x; a0.y += v0.y; a0.z += v0.z; a0.w += v0.w;
        a1.x += v1.x; a1.y += v1.y; a1.z += v1.z; a1.w += v1.w;
        a2.x += v2.x; a2.y += v2.y; a2.z += v2.z; a2.w += v2.w;
        a3.x += v3.x; a3.y += v3.y; a3.z += v3.z; a3.w += v3.w;
    }
    for (; e < end; e++) {
        int s = g_csr[e];
        float4 v = H[s * 16 + lane];
        a0.x += v.x; a0.y += v.y; a0.z += v.z; a0.w += v.w;
    }
    float4 bv = reinterpret_cast<const float4*>(b2)[lane];
    float4 o = make_float4(a0.x + a1.x + a2.x + a3.x + bv.x,
                           a0.y + a1.y + a2.y + a3.y + bv.y,
                           a0.z + a1.z + a2.z + a3.z + bv.z,
                           a0.w + a1.w + a2.w + a3.w + bv.w);
    reinterpret_cast<float4*>(outp)[ghw * 16 + lane] = o;
}

extern "C" void kernel_launch(void* const* d_in, const int* in_sizes, int n_in,
                              void* d_out, int out_size) {
    const float* x  = (const float*)d_in[0];
    const int*   ei = (const int*)d_in[1];   // [2, E]: src then dst
    const float* W1 = (const float*)d_in[2];
    const float* b1 = (const float*)d_in[3];
    const float* W2 = (const float*)d_in[4];
    const float* b2 = (const float*)d_in[5];
    float* outp = (float*)d_out;

    const int* src = ei;
    const int* dst = ei + EDGES;

    // resolve device-global addresses
    uint32_t *w1h, *w1l, *w2h, *w2l;
    void *odeg_p, *cnt_p;
    cudaGetSymbolAddress((void**)&w1h, g_w1h);
    cudaGetSymbolAddress((void**)&w1l, g_w1l);
    cudaGetSymbolAddress((void**)&w2h, g_w2h);
    cudaGetSymbolAddress((void**)&w2l, g_w2l);
    cudaGetSymbolAddress(&odeg_p, g_odeg);
    cudaGetSymbolAddress(&cnt_p, g_cnt);

    // ---- CSR build + out-degree + weight split ----
    cudaMemsetAsync(odeg_p, 0, NODES * sizeof(int));
    cudaMemsetAsync(cnt_p, 0, NODES * sizeof(int));
    wsplit_kernel<<<((IN_C / 2) * HID_C + 255) / 256, 256>>>(W1, W2);
    hist_kernel<<<(EDGES + 255) / 256, 256>>>(src, dst);
    scan1_kernel<<<SCAN_NB, SCAN_B>>>();
    scan2_kernel<<<1, 32>>>();
    scan3_kernel<<<SCAN_NB, SCAN_B>>>();   // also computes deg_inv
    fill_kernel<<<(EDGES + 255) / 256, 256>>>(src, dst);

    // ---- layer 1: h1 = (x @ W1) * deg_inv ; out1 = b1 + sum_in h1 ----
    {
        dim3 grid(HID_C / 64, (NODES + 127) / 128);
        gemm_tc_kernel<HID_C, false><<<grid, 256>>>(x, w1h, w1l, NODES);
    }
    {
        long long threads = (long long)NODES * 32;
        agg128_kernel<<<(unsigned)((threads + 255) / 256), 256>>>(b1);
    }

    // ---- layer 2: h2 = (relu(out1) @ W2) * deg_inv ; out = b2 + sum_in h2 ----
    {
        dim3 grid(OUT_C / 64, (NODES + 127) / 128);
        gemm_tc_kernel<OUT_C, true><<<grid, 256>>>(nullptr, w2h, w2l, NODES);
    }
    {
        long long threads = (long long)NODES * 16;
        agg64_kernel<<<(unsigned)((threads + 255) / 256), 256>>>(b2, outp);
    }
}

// round 15
// speedup vs baseline: 2.1200x; 1.0216x over previous
#include <cuda_runtime.h>
#include <cuda_bf16.h>
#include <cstdint>

// Problem constants (fixed by the reference)
#define NODES 100000
#define EDGES 1600000
#define IN_C  128
#define HID_C 128
#define OUT_C 64

#define SCAN_B 1024
#define SCAN_NB ((NODES + SCAN_B - 1) / SCAN_B)   // 98

// -------- scratch (no allocation allowed -> __device__ globals) --------
__device__ int   g_odeg[NODES];          // out-degree (src histogram)
__device__ float g_deginv[NODES];
__device__ int   g_cnt[NODES];           // in-degree (dst histogram)
__device__ int   g_off[NODES + 1];       // CSR offsets (by dst)
__device__ int   g_cur[NODES];           // fill cursors
__device__ int   g_csr[EDGES];           // src ids grouped by dst
__device__ int   g_bsum[SCAN_NB + 1];    // scan block sums
__device__ float g_h1[NODES * HID_C];    // scaled projection, layer 1
__device__ float g_out1[NODES * HID_C];  // relu input (aggregated + b1)
__device__ float g_h2[NODES * OUT_C];    // scaled projection, layer 2
// pre-split, k-pair-packed weights: [K/2][N] of uint32 {lo=bf16(W[2k]), hi=bf16(W[2k+1])}
__device__ uint32_t g_w1h[(IN_C / 2) * HID_C];
__device__ uint32_t g_w1l[(IN_C / 2) * HID_C];
__device__ uint32_t g_w2h[(HID_C / 2) * OUT_C];
__device__ uint32_t g_w2l[(HID_C / 2) * OUT_C];

// -------- histograms: out-degree of src, in-degree of dst --------
__global__ void hist_kernel(const int* __restrict__ src,
                            const int* __restrict__ dst) {
    int i = blockIdx.x * blockDim.x + threadIdx.x;
    if (i < EDGES) {
        atomicAdd(&g_odeg[src[i]], 1);
        atomicAdd(&g_cnt[dst[i]], 1);
    }
}

// -------- weight split: W -> bf16 hi + bf16 residual, k-pair packed --------
__device__ __forceinline__ uint32_t pack_bf16_pair(float x0, float x1) {
    uint32_t r;
    asm("cvt.rn.bf16x2.f32 %0, %1, %2;" : "=r"(r) : "f"(x1), "f"(x0));
    return r;
}

__global__ void wsplit_kernel(const float* __restrict__ W1,
                              const float* __restrict__ W2) {
    int i = blockIdx.x * blockDim.x + threadIdx.x;
    if (i < (IN_C / 2) * HID_C) {
        int kp = i / HID_C, n = i % HID_C;
        float w0 = W1[(2 * kp) * HID_C + n];
        float w1 = W1[(2 * kp + 1) * HID_C + n];
        uint32_t h = pack_bf16_pair(w0, w1);
        float h0 = __uint_as_float(h << 16);
        float h1 = __uint_as_float(h & 0xFFFF0000u);
        g_w1h[i] = h;
        g_w1l[i] = pack_bf16_pair(w0 - h0, w1 - h1);
    }
    if (i < (HID_C / 2) * OUT_C) {
        int kp = i / OUT_C, n = i % OUT_C;
        float w0 = W2[(2 * kp) * OUT_C + n];
        float w1 = W2[(2 * kp + 1) * OUT_C + n];
        uint32_t h = pack_bf16_pair(w0, w1);
        float h0 = __uint_as_float(h << 16);
        float h1 = __uint_as_float(h & 0xFFFF0000u);
        g_w2h[i] = h;
        g_w2l[i] = pack_bf16_pair(w0 - h0, w1 - h1);
    }
}

// -------- 3-kernel exclusive scan of g_cnt -> g_off --------
__global__ __launch_bounds__(SCAN_B) void scan1_kernel() {
    int gi = blockIdx.x * SCAN_B + threadIdx.x;
    int v = (gi < NODES) ? g_cnt[gi] : 0;
    int lane = threadIdx.x & 31, w = threadIdx.x >> 5;
    int x = v;
#pragma unroll
    for (int o = 1; o < 32; o <<= 1) {
        int y = __shfl_up_sync(0xffffffffu, x, o);
        if (lane >= o) x += y;
    }
    __shared__ int wsum[32];
    if (lane == 31) wsum[w] = x;
    __syncthreads();
    if (w == 0) {
        int s = wsum[lane];
#pragma unroll
        for (int o = 1; o < 32; o <<= 1) {
            int y = __shfl_up_sync(0xffffffffu, s, o);
            if (lane >= o) s += y;
        }
        wsum[lane] = s;
    }
    __syncthreads();
    int incl = x + (w > 0 ? wsum[w - 1] : 0);
    if (gi < NODES) g_off[gi] = incl - v;           // block-local exclusive
    if (threadIdx.x == SCAN_B - 1) g_bsum[blockIdx.x] = incl;
}

// single-warp shfl scan over the 98 block sums (was a 1-thread serial loop)
__global__ void scan2_kernel() {
    int lane = threadIdx.x;          // 32 threads
    int base = lane * 4;
    int v[4];
#pragma unroll
    for (int j = 0; j < 4; j++) {
        int idx = base + j;
        v[j] = (idx < SCAN_NB) ? g_bsum[idx] : 0;
    }
    int local = v[0] + v[1] + v[2] + v[3];
    int x = local;
#pragma unroll
    for (int o = 1; o < 32; o <<= 1) {
        int y = __shfl_up_sync(0xffffffffu, x, o);
        if (lane >= o) x += y;
    }
    int run = x - local;             // exclusive prefix of this thread's chunk
#pragma unroll
    for (int j = 0; j < 4; j++) {
        int idx = base + j;
        if (idx < SCAN_NB) {
            int t = v[j];
            g_bsum[idx] = run;
            run += t;
        }
    }
}

// scan3 + deg_inv fused
__global__ __launch_bounds__(SCAN_B) void scan3_kernel() {
    int gi = blockIdx.x * SCAN_B + threadIdx.x;
    if (gi < NODES) {
        int o = g_off[gi] + g_bsum[blockIdx.x];
        g_off[gi] = o;
        g_cur[gi] = o;
        g_deginv[gi] = 1.0f / fmaxf((float)g_odeg[gi], 1.0f);
    }
    if (gi == 0) g_off[NODES] = EDGES;
}

// -------- CSR fill: bucket src ids by dst --------
__global__ void fill_kernel(const int* __restrict__ src,
                            const int* __restrict__ dst) {
    int i = blockIdx.x * blockDim.x + threadIdx.x;
    if (i < EDGES) {
        int p = atomicAdd(&g_cur[dst[i]], 1);
        g_csr[p] = src[i];
    }
}

// ===================== split-BF16 tensor-core GEMM =====================
// C[M,NOUT] = op(A[M,128]) @ B[128,NOUT], scaled by deg_inv[row].
// a = ah + al (bf16 hi + bf16 residual); B pre-split the same way.
// D += ah*bh + ah*bl + al*bh  ->  ~eps_bf16^2 accuracy.
// Tile: BM=128, BN=64, KC=32. 256 threads = 8 warps; warp = 16 rows x 64 cols.

__device__ __forceinline__ void mma_bf16(float c[4],
                                         uint32_t a0, uint32_t a1, uint32_t a2, uint32_t a3,
                                         uint32_t b0, uint32_t b1) {
    asm volatile(
        "mma.sync.aligned.m16n8k16.row.col.f32.bf16.bf16.f32 "
        "{%0,%1,%2,%3}, {%4,%5,%6,%7}, {%8,%9}, {%0,%1,%2,%3};\n"
        : "+f"(c[0]), "+f"(c[1]), "+f"(c[2]), "+f"(c[3])
        : "r"(a0), "r"(a1), "r"(a2), "r"(a3), "r"(b0), "r"(b1));
}

__device__ __forceinline__ void split_pair(float x0, float x1,
                                           uint32_t& h, uint32_t& l) {
    h = pack_bf16_pair(x0, x1);
    float h0 = __uint_as_float(h << 16);
    float h1 = __uint_as_float(h & 0xFFFF0000u);
    l = pack_bf16_pair(x0 - h0, x1 - h1);
}

template <int NOUT, bool SECOND>
__global__ __launch_bounds__(256) void gemm_tc_kernel(const float* __restrict__ Ain,
                                                      const uint32_t* __restrict__ Bh,
                                                      const uint32_t* __restrict__ Bl,
                                                      int M) {
    constexpr int BM = 128, BN = 64, KC = 32;
    constexpr int APITCH = 40;
    constexpr int BPITCH = 72;

    const float* A = SECOND ? g_out1 : Ain;
    float*       C = SECOND ? g_h2   : g_h1;

    __shared__ float    As [BM * APITCH];
    __shared__ uint32_t Bsh[(KC / 2) * BPITCH];
    __shared__ uint32_t Bsl[(KC / 2) * BPITCH];

    const int tid  = threadIdx.x;
    const int lane = tid & 31;
    const int wid  = tid >> 5;
    const int rowBase = blockIdx.y * BM;
    const int colBase = blockIdx.x * BN;
    const int wrow = wid * 16;

    const int g = lane >> 2;
    const int t = lane & 3;

    float c[8][4];
#pragma unroll
    for (int nt = 0; nt < 8; nt++)
#pragma unroll
        for (int j = 0; j < 4; j++) c[nt][j] = 0.0f;

    for (int k0 = 0; k0 < 128; k0 += KC) {
#pragma unroll
        for (int i = tid; i < BM * KC / 4; i += 256) {
            int r = i >> 3;
            int q = i & 7;
            int grow = rowBase + r;
            float4 a = make_float4(0.f, 0.f, 0.f, 0.f);
            if (grow < M)
                a = *reinterpret_cast<const float4*>(A + (size_t)grow * 128 + k0 + q * 4);
            if (SECOND) {
                a.x = fmaxf(a.x, 0.f); a.y = fmaxf(a.y, 0.f);
                a.z = fmaxf(a.z, 0.f); a.w = fmaxf(a.w, 0.f);
            }
            *reinterpret_cast<float4*>(&As[r * APITCH + q * 4]) = a;
        }
        {
            int kp = tid >> 4;
            int nq = tid & 15;
            size_t goff = (size_t)(k0 / 2 + kp) * NOUT + colBase + nq * 4;
            *reinterpret_cast<uint4*>(&Bsh[kp * BPITCH + nq * 4]) =
                *reinterpret_cast<const uint4*>(Bh + goff);
            *reinterpret_cast<uint4*>(&Bsl[kp * BPITCH + nq * 4]) =
                *reinterpret_cast<const uint4*>(Bl + goff);
        }
        __syncthreads();

#pragma unroll
        for (int kk = 0; kk < KC; kk += 16) {
            float2 p0 = *reinterpret_cast<const float2*>(&As[(wrow + g)     * APITCH + kk + 2 * t]);
            float2 p1 = *reinterpret_cast<const float2*>(&As[(wrow + g + 8) * APITCH + kk + 2 * t]);
            float2 p2 = *reinterpret_cast<const float2*>(&As[(wrow + g)     * APITCH + kk + 2 * t + 8]);
            float2 p3 = *reinterpret_cast<const float2*>(&As[(wrow + g + 8) * APITCH + kk + 2 * t + 8]);
            uint32_t ah0, al0, ah1, al1, ah2, al2, ah3, al3;
            split_pair(p0.x, p0.y, ah0, al0);
            split_pair(p1.x, p1.y, ah1, al1);
            split_pair(p2.x, p2.y, ah2, al2);
            split_pair(p3.x, p3.y, ah3, al3);

            const int kb = kk / 2;
#pragma unroll
            for (int nt = 0; nt < 8; nt++) {
                uint32_t bh0 = Bsh[(kb + t)     * BPITCH + nt * 8 + g];
                uint32_t bh1 = Bsh[(kb + t + 4) * BPITCH + nt * 8 + g];
                uint32_t bl0 = Bsl[(kb + t)     * BPITCH + nt * 8 + g];
                uint32_t bl1 = Bsl[(kb + t + 4) * BPITCH + nt * 8 + g];
                mma_bf16(c[nt], ah0, ah1, ah2, ah3, bh0, bh1);
                mma_bf16(c[nt], ah0, ah1, ah2, ah3, bl0, bl1);
                mma_bf16(c[nt], al0, al1, al2, al3, bh0, bh1);
            }
        }
        __syncthreads();
    }

    // ---- epilogue: scale by deg_inv[row], store ----
    int r0 = rowBase + wrow + g;
    int r1 = r0 + 8;
    float s0 = (r0 < M) ? g_deginv[r0] : 0.f;
    float s1 = (r1 < M) ? g_deginv[r1] : 0.f;
#pragma unroll
    for (int nt = 0; nt < 8; nt++) {
        int col = colBase + nt * 8 + 2 * t;
        if (r0 < M) {
            float2 o = make_float2(c[nt][0] * s0, c[nt][1] * s0);
            *reinterpret_cast<float2*>(C + (size_t)r0 * NOUT + col) = o;
        }
        if (r1 < M) {
            float2 o = make_float2(c[nt][2] * s1, c[nt][3] * s1);
            *reinterpret_cast<float2*>(C + (size_t)r1 * NOUT + col) = o;
        }
    }
}

// -------- layer-1 aggregate: warp per dst node, 32 x float4 = 128 ch ------
__global__ __launch_bounds__(256) void agg128_kernel(const float* __restrict__ b1) {
    int gw = (blockIdx.x * blockDim.x + threadIdx.x) >> 5;
    int lane = threadIdx.x & 31;
    if (gw >= NODES) return;
    int beg = g_off[gw], end = g_off[gw + 1];
    const float4* __restrict__ H = reinterpret_cast<const float4*>(g_h1);

    float4 a0 = make_float4(0.f, 0.f, 0.f, 0.f);
    float4 a1 = make_float4(0.f, 0.f, 0.f, 0.f);
    float4 a2 = make_float4(0.f, 0.f, 0.f, 0.f);
    float4 a3 = make_float4(0.f, 0.f, 0.f, 0.f);
    int e = beg;
    for (; e + 3 < end; e += 4) {
        int s0 = g_csr[e];
        int s1 = g_csr[e + 1];
        int s2 = g_csr[e + 2];
        int s3 = g_csr[e + 3];
        float4 v0 = H[s0 * 32 + lane];
        float4 v1 = H[s1 * 32 + lane];
        float4 v2 = H[s2 * 32 + lane];
        float4 v3 = H[s3 * 32 + lane];
        a0.x += v0.x; a0.y += v0.y; a0.z += v0.z; a0.w += v0.w;
        a1.x += v1.x; a1.y += v1.y; a1.z += v1.z; a1.w += v1.w;
        a2.x += v2.x; a2.y += v2.y; a2.z += v2.z; a2.w += v2.w;
        a3.x += v3.x; a3.y += v3.y; a3.z += v3.z; a3.w += v3.w;
    }
    for (; e < end; e++) {
        int s = g_csr[e];
        float4 v = H[s * 32 + lane];
        a0.x += v.x; a0.y += v.y; a0.z += v.z; a0.w += v.w;
    }
    float4 bv = reinterpret_cast<const float4*>(b1)[lane];
    float4 o = make_float4(a0.x + a1.x + a2.x + a3.x + bv.x,
                           a0.y + a1.y + a2.y + a3.y + bv.y,
                           a0.z + a1.z + a2.z + a3.z + bv.z,
                           a0.w + a1.w + a2.w + a3.w + bv.w);
    reinterpret_cast<float4*>(g_out1)[gw * 32 + lane] = o;
}

// -------- layer-2 aggregate: HALF-warp per dst node, 16 x float4 = 64 ch --
__global__ __launch_bounds__(256) void agg64_kernel(const float* __restrict__ b2,
                                                    float* __restrict__ outp) {
    int ghw = (blockIdx.x * blockDim.x + threadIdx.x) >> 4;
    int lane = threadIdx.x & 15;
    if (ghw >= NODES) return;
    int beg = g_off[ghw], end = g_off[ghw + 1];
    const float4* __restrict__ H = reinterpret_cast<const float4*>(g_h2);

    float4 a0 = make_float4(0.f, 0.f, 0.f, 0.f);
    float4 a1 = make_float4(0.f, 0.f, 0.f, 0.f);
    float4 a2 = make_float4(0.f, 0.f, 0.f, 0.f);
    float4 a3 = make_float4(0.f, 0.f, 0.f, 0.f);
    int e = beg;
    for (; e + 3 < end; e += 4) {
        int s0 = g_csr[e];
        int s1 = g_csr[e + 1];
        int s2 = g_csr[e + 2];
        int s3 = g_csr[e + 3];
        float4 v0 = H[s0 * 16 + lane];
        float4 v1 = H[s1 * 16 + lane];
        float4 v2 = H[s2 * 16 + lane];
        float4 v3 = H[s3 * 16 + lane];
        a0.x += v0.x; a0.y += v0.y; a0.z += v0.z; a0.w += v0.w;
        a1.x += v1.x; a1.y += v1.y; a1.z += v1.z; a1.w += v1.w;
        a2.x += v2.x; a2.y += v2.y; a2.z += v2.z; a2.w += v2.w;
        a3.x += v3.x; a3.y += v3.y; a3.z += v3.z; a3.w += v3.w;
    }
    for (; e < end; e++) {
        int s = g_csr[e];
        float4 v = H[s * 16 + lane];
        a0.x += v.x; a0.y += v.y; a0.z += v.z; a0.w += v.w;
    }
    float4 bv = reinterpret_cast<const float4*>(b2)[lane];
    float4 o = make_float4(a0.x + a1.x + a2.x + a3.x + bv.x,
                           a0.y + a1.y + a2.y + a3.y + bv.y,
                           a0.z + a1.z + a2.z + a3.z + bv.z,
                           a0.w + a1.w + a2.w + a3.w + bv.w);
    reinterpret_cast<float4*>(outp)[ghw * 16 + lane] = o;
}

extern "C" void kernel_launch(void* const* d_in, const int* in_sizes, int n_in,
                              void* d_out, int out_size) {
    const float* x  = (const float*)d_in[0];
    const int*   ei = (const int*)d_in[1];   // [2, E]: src then dst
    const float* W1 = (const float*)d_in[2];
    const float* b1 = (const float*)d_in[3];
    const float* W2 = (const float*)d_in[4];
    const float* b2 = (const float*)d_in[5];
    float* outp = (float*)d_out;

    const int* src = ei;
    const int* dst = ei + EDGES;

    // resolve device-global addresses
    uint32_t *w1h, *w1l, *w2h, *w2l;
    void *odeg_p, *cnt_p;
    cudaGetSymbolAddress((void**)&w1h, g_w1h);
    cudaGetSymbolAddress((void**)&w1l, g_w1l);
    cudaGetSymbolAddress((void**)&w2h, g_w2h);
    cudaGetSymbolAddress((void**)&w2l, g_w2l);
    cudaGetSymbolAddress(&odeg_p, g_odeg);
    cudaGetSymbolAddress(&cnt_p, g_cnt);

    // ---- CSR build + out-degree + weight split (single stream) ----
    cudaMemsetAsync(odeg_p, 0, NODES * sizeof(int));
    cudaMemsetAsync(cnt_p, 0, NODES * sizeof(int));
    wsplit_kernel<<<((IN_C / 2) * HID_C + 255) / 256, 256>>>(W1, W2);
    hist_kernel<<<(EDGES + 255) / 256, 256>>>(src, dst);
    scan1_kernel<<<SCAN_NB, SCAN_B>>>();
    scan2_kernel<<<1, 32>>>();
    scan3_kernel<<<SCAN_NB, SCAN_B>>>();   // also computes deg_inv
    fill_kernel<<<(EDGES + 255) / 256, 256>>>(src, dst);

    // ---- layer 1: h1 = (x @ W1) * deg_inv ; out1 = b1 + sum_in h1 ----
    {
        dim3 grid(HID_C / 64, (NODES + 127) / 128);
        gemm_tc_kernel<HID_C, false><<<grid, 256>>>(x, w1h, w1l, NODES);
    }
    {
        long long threads = (long long)NODES * 32;
        agg128_kernel<<<(unsigned)((threads + 255) / 256), 256>>>(b1);
    }

    // ---- layer 2: h2 = (relu(out1) @ W2) * deg_inv ; out = b2 + sum_in h2 ----
    {
        dim3 grid(OUT_C / 64, (NODES + 127) / 128);
        gemm_tc_kernel<OUT_C, true><<<grid, 256>>>(nullptr, w2h, w2l, NODES);
    }
    {
        long long threads = (long long)NODES * 16;
        agg64_kernel<<<(unsigned)((threads + 255) / 256), 256>>>(b2, outp);
    }
}